// round 2
// baseline (speedup 1.0000x reference)
#include <cuda_runtime.h>

#define B_DIM   2
#define T_DIM   2048
#define E_DIM   1024
#define HEADS   16
#define HD      64
#define NROWS   (B_DIM * T_DIM)   // 4096
#define FF_DIM  (4 * E_DIM)       // 4096

// ---------------- scratch (no allocations allowed) ----------------
__device__ float g_xn1[NROWS * E_DIM];
__device__ float g_q  [NROWS * E_DIM];
__device__ float g_k  [NROWS * E_DIM];
__device__ float g_v  [NROWS * E_DIM];
__device__ float g_att[NROWS * E_DIM];
__device__ float g_x2 [NROWS * E_DIM];
__device__ float g_h2 [NROWS * E_DIM];
__device__ float g_ff [NROWS * FF_DIM];

// ---------------- LayerNorm: one block per row ----------------
__global__ void ln_kernel(const float* __restrict__ X,
                          const float* __restrict__ gw,
                          const float* __restrict__ bw,
                          float* __restrict__ Y)
{
    int row = blockIdx.x;
    int tid = threadIdx.x;                 // 256 threads, 4 floats each
    const float4* x4 = (const float4*)(X + (size_t)row * E_DIM);
    float4 v = x4[tid];
    float s  = v.x + v.y + v.z + v.w;
    float s2 = v.x*v.x + v.y*v.y + v.z*v.z + v.w*v.w;
    #pragma unroll
    for (int o = 16; o > 0; o >>= 1) {
        s  += __shfl_xor_sync(0xffffffffu, s,  o);
        s2 += __shfl_xor_sync(0xffffffffu, s2, o);
    }
    __shared__ float ss[8], ss2[8];
    int w = tid >> 5;
    if ((tid & 31) == 0) { ss[w] = s; ss2[w] = s2; }
    __syncthreads();
    if (w == 0) {
        s  = ss [tid & 7];
        s2 = ss2[tid & 7];
        #pragma unroll
        for (int o = 4; o > 0; o >>= 1) {
            s  += __shfl_xor_sync(0xffffffffu, s,  o);
            s2 += __shfl_xor_sync(0xffffffffu, s2, o);
        }
        if (tid == 0) { ss[0] = s; ss2[0] = s2; }
    }
    __syncthreads();
    float mu  = ss[0]  * (1.0f / E_DIM);
    float var = ss2[0] * (1.0f / E_DIM) - mu * mu;
    float r   = rsqrtf(var + 1e-5f);
    float4 g4 = ((const float4*)gw)[tid];
    float4 b4 = ((const float4*)bw)[tid];
    float4 o;
    o.x = (v.x - mu) * r * g4.x + b4.x;
    o.y = (v.y - mu) * r * g4.y + b4.y;
    o.z = (v.z - mu) * r * g4.z + b4.z;
    o.w = (v.w - mu) * r * g4.w + b4.w;
    ((float4*)(Y + (size_t)row * E_DIM))[tid] = o;
}

// ---------------- SGEMM: C = A(MxK) @ B(KxN) [+bias][+relu|+res] ----------------
// 128x128 tile, BK=8, 256 threads, 8x8 per thread.
// EPI: 0 = none, 2 = bias+relu, 3 = bias+residual
template<int EPI>
__global__ void sgemm(const float* __restrict__ A, const float* __restrict__ Bm,
                      const float* __restrict__ bias, const float* __restrict__ res,
                      float* __restrict__ C, int M, int N, int K)
{
    __shared__ float As[8][128];
    __shared__ float Bs[8][128];
    int tid = threadIdx.x;
    int bm = blockIdx.y * 128, bn = blockIdx.x * 128;
    int tx = tid & 15, ty = tid >> 4;

    int arow = tid >> 1;          // 0..127
    int acol = (tid & 1) * 4;     // 0 or 4
    int brow = tid >> 5;          // 0..7
    int bcol = (tid & 31) * 4;    // 0..124

    const float* Aptr = A + (size_t)(bm + arow) * K + acol;
    const float* Bptr = Bm + (size_t)brow * N + bn + bcol;

    float acc[8][8];
    #pragma unroll
    for (int i = 0; i < 8; i++)
        #pragma unroll
        for (int j = 0; j < 8; j++) acc[i][j] = 0.f;

    for (int k0 = 0; k0 < K; k0 += 8) {
        float4 a4 = *(const float4*)Aptr;
        float4 b4 = *(const float4*)Bptr;
        __syncthreads();
        As[acol + 0][arow] = a4.x;
        As[acol + 1][arow] = a4.y;
        As[acol + 2][arow] = a4.z;
        As[acol + 3][arow] = a4.w;
        *(float4*)&Bs[brow][bcol] = b4;
        __syncthreads();
        #pragma unroll
        for (int kk = 0; kk < 8; kk++) {
            float af[8], bf[8];
            *(float4*)(af)     = *(float4*)&As[kk][ty * 8];
            *(float4*)(af + 4) = *(float4*)&As[kk][ty * 8 + 4];
            *(float4*)(bf)     = *(float4*)&Bs[kk][tx * 8];
            *(float4*)(bf + 4) = *(float4*)&Bs[kk][tx * 8 + 4];
            #pragma unroll
            for (int i = 0; i < 8; i++)
                #pragma unroll
                for (int j = 0; j < 8; j++)
                    acc[i][j] = fmaf(af[i], bf[j], acc[i][j]);
        }
        Aptr += 8;
        Bptr += (size_t)8 * N;
    }

    #pragma unroll
    for (int i = 0; i < 8; i++) {
        int row = bm + ty * 8 + i;
        #pragma unroll
        for (int j = 0; j < 8; j += 4) {
            int col = bn + tx * 8 + j;
            float4 o;
            o.x = acc[i][j + 0]; o.y = acc[i][j + 1];
            o.z = acc[i][j + 2]; o.w = acc[i][j + 3];
            if (EPI >= 2) {
                float4 bb = *(const float4*)(bias + col);
                o.x += bb.x; o.y += bb.y; o.z += bb.z; o.w += bb.w;
            }
            if (EPI == 2) {
                o.x = fmaxf(o.x, 0.f); o.y = fmaxf(o.y, 0.f);
                o.z = fmaxf(o.z, 0.f); o.w = fmaxf(o.w, 0.f);
            }
            if (EPI == 3) {
                float4 rr = *(const float4*)(res + (size_t)row * N + col);
                o.x += rr.x; o.y += rr.y; o.z += rr.z; o.w += rr.w;
            }
            *(float4*)(C + (size_t)row * N + col) = o;
        }
    }
}

// ---------------- causal flash attention (fp32) ----------------
// block = 128 threads = 128 query rows for one (b,h). Key tiles of 32.
__global__ void attn_kernel(const float* __restrict__ Q, const float* __restrict__ K,
                            const float* __restrict__ V, float* __restrict__ O)
{
    __shared__ float Ks[32][64];
    __shared__ float Vs[32][64];
    __shared__ float Ps[32][128];
    int b = blockIdx.z, h = blockIdx.y;
    int q0 = blockIdx.x * 128;
    int tid = threadIdx.x;
    int qi = q0 + tid;

    const float* qp = Q + ((size_t)(b * T_DIM + qi)) * E_DIM + h * HD;
    float qreg[HD];
    #pragma unroll
    for (int d = 0; d < HD; d += 4) *(float4*)(qreg + d) = *(const float4*)(qp + d);

    float acc[HD];
    #pragma unroll
    for (int d = 0; d < HD; d++) acc[d] = 0.f;
    float m = -1e30f, l = 0.f;

    int ntiles = blockIdx.x * 4 + 4;   // keys up to q0+127 inclusive
    for (int t = 0; t < ntiles; t++) {
        int kt = t * 32;
        __syncthreads();
        for (int i = tid; i < 32 * 16; i += 128) {
            int r = i >> 4, c = (i & 15) << 2;
            size_t g = ((size_t)(b * T_DIM + kt + r)) * E_DIM + h * HD + c;
            *(float4*)&Ks[r][c] = *(const float4*)(K + g);
            *(float4*)&Vs[r][c] = *(const float4*)(V + g);
        }
        __syncthreads();

        float mt = m;
        int jmax = qi - kt;
        #pragma unroll 2
        for (int j = 0; j < 32; j++) {
            float s = 0.f;
            #pragma unroll
            for (int d = 0; d < HD; d += 4) {
                float4 k4 = *(const float4*)&Ks[j][d];
                s = fmaf(qreg[d + 0], k4.x, s);
                s = fmaf(qreg[d + 1], k4.y, s);
                s = fmaf(qreg[d + 2], k4.z, s);
                s = fmaf(qreg[d + 3], k4.w, s);
            }
            s *= 0.125f;                       // 1/sqrt(64)
            s = (j <= jmax) ? s : -1e30f;      // causal mask
            Ps[j][tid] = s;
            mt = fmaxf(mt, s);
        }

        float corr = __expf(m - mt);
        l *= corr;
        #pragma unroll
        for (int d = 0; d < HD; d++) acc[d] *= corr;

        #pragma unroll 2
        for (int j = 0; j < 32; j++) {
            float pj = __expf(Ps[j][tid] - mt);
            l += pj;
            #pragma unroll
            for (int d = 0; d < HD; d += 4) {
                float4 v4 = *(const float4*)&Vs[j][d];
                acc[d + 0] = fmaf(pj, v4.x, acc[d + 0]);
                acc[d + 1] = fmaf(pj, v4.y, acc[d + 1]);
                acc[d + 2] = fmaf(pj, v4.z, acc[d + 2]);
                acc[d + 3] = fmaf(pj, v4.w, acc[d + 3]);
            }
        }
        m = mt;
    }

    float inv = 1.0f / l;
    float* op = O + ((size_t)(b * T_DIM + qi)) * E_DIM + h * HD;
    #pragma unroll
    for (int d = 0; d < HD; d += 4) {
        float4 o;
        o.x = acc[d + 0] * inv; o.y = acc[d + 1] * inv;
        o.z = acc[d + 2] * inv; o.w = acc[d + 3] * inv;
        *(float4*)(op + d) = o;
    }
}

// ---------------- launch ----------------
extern "C" void kernel_launch(void* const* d_in, const int* in_sizes, int n_in,
                              void* d_out, int out_size)
{
    const float* x     = (const float*)d_in[0];
    const float* ln1_g = (const float*)d_in[1];
    const float* ln1_b = (const float*)d_in[2];
    const float* Wq    = (const float*)d_in[3];
    const float* Wk    = (const float*)d_in[4];
    const float* Wv    = (const float*)d_in[5];
    const float* Wo    = (const float*)d_in[6];
    const float* bo    = (const float*)d_in[7];
    const float* ln2_g = (const float*)d_in[8];
    const float* ln2_b = (const float*)d_in[9];
    const float* W1    = (const float*)d_in[10];
    const float* b1    = (const float*)d_in[11];
    const float* W2    = (const float*)d_in[12];
    const float* b2    = (const float*)d_in[13];
    float* out = (float*)d_out;

    float *xn1, *q, *k, *v, *att, *x2, *h2, *ff;
    cudaGetSymbolAddress((void**)&xn1, g_xn1);
    cudaGetSymbolAddress((void**)&q,   g_q);
    cudaGetSymbolAddress((void**)&k,   g_k);
    cudaGetSymbolAddress((void**)&v,   g_v);
    cudaGetSymbolAddress((void**)&att, g_att);
    cudaGetSymbolAddress((void**)&x2,  g_x2);
    cudaGetSymbolAddress((void**)&h2,  g_h2);
    cudaGetSymbolAddress((void**)&ff,  g_ff);

    dim3 gE(E_DIM / 128, NROWS / 128);    // (8, 32)
    dim3 gF(FF_DIM / 128, NROWS / 128);   // (32, 32)

    ln_kernel<<<NROWS, 256>>>(x, ln1_g, ln1_b, xn1);
    sgemm<0><<<gE, 256>>>(xn1, Wq, nullptr, nullptr, q, NROWS, E_DIM, E_DIM);
    sgemm<0><<<gE, 256>>>(xn1, Wk, nullptr, nullptr, k, NROWS, E_DIM, E_DIM);
    sgemm<0><<<gE, 256>>>(xn1, Wv, nullptr, nullptr, v, NROWS, E_DIM, E_DIM);
    attn_kernel<<<dim3(T_DIM / 128, HEADS, B_DIM), 128>>>(q, k, v, att);
    sgemm<3><<<gE, 256>>>(att, Wo, bo, x, x2, NROWS, E_DIM, E_DIM);
    ln_kernel<<<NROWS, 256>>>(x2, ln2_g, ln2_b, h2);
    sgemm<2><<<gF, 256>>>(h2, W1, b1, nullptr, ff, NROWS, FF_DIM, E_DIM);
    sgemm<3><<<gE, 256>>>(ff, W2, b2, x2, out, NROWS, E_DIM, FF_DIM);
}

// round 3
// speedup vs baseline: 1.8112x; 1.8112x over previous
#include <cuda_runtime.h>

#define B_DIM   2
#define T_DIM   2048
#define E_DIM   1024
#define HEADS   16
#define HD      64
#define NROWS   (B_DIM * T_DIM)   // 4096
#define FF_DIM  (4 * E_DIM)       // 4096

// ---------------- scratch (no allocations allowed) ----------------
__device__ float g_xn1[NROWS * E_DIM];
__device__ float g_q  [NROWS * E_DIM];
__device__ float g_k  [NROWS * E_DIM];
__device__ float g_v  [NROWS * E_DIM];
__device__ float g_att[NROWS * E_DIM];
__device__ float g_x2 [NROWS * E_DIM];
__device__ float g_h2 [NROWS * E_DIM];
__device__ float g_ff [NROWS * FF_DIM];

__device__ __forceinline__ unsigned f2tf32(float x) {
    unsigned u;
    asm("cvt.rna.tf32.f32 %0, %1;" : "=r"(u) : "f"(x));
    return u;
}

// ---------------- LayerNorm: one block per row ----------------
__global__ void ln_kernel(const float* __restrict__ X,
                          const float* __restrict__ gw,
                          const float* __restrict__ bw,
                          float* __restrict__ Y)
{
    int row = blockIdx.x;
    int tid = threadIdx.x;                 // 256 threads, 4 floats each
    const float4* x4 = (const float4*)(X + (size_t)row * E_DIM);
    float4 v = x4[tid];
    float s  = v.x + v.y + v.z + v.w;
    float s2 = v.x*v.x + v.y*v.y + v.z*v.z + v.w*v.w;
    #pragma unroll
    for (int o = 16; o > 0; o >>= 1) {
        s  += __shfl_xor_sync(0xffffffffu, s,  o);
        s2 += __shfl_xor_sync(0xffffffffu, s2, o);
    }
    __shared__ float ss[8], ss2[8];
    int w = tid >> 5;
    if ((tid & 31) == 0) { ss[w] = s; ss2[w] = s2; }
    __syncthreads();
    if (w == 0) {
        s  = ss [tid & 7];
        s2 = ss2[tid & 7];
        #pragma unroll
        for (int o = 4; o > 0; o >>= 1) {
            s  += __shfl_xor_sync(0xffffffffu, s,  o);
            s2 += __shfl_xor_sync(0xffffffffu, s2, o);
        }
        if (tid == 0) { ss[0] = s; ss2[0] = s2; }
    }
    __syncthreads();
    float mu  = ss[0]  * (1.0f / E_DIM);
    float var = ss2[0] * (1.0f / E_DIM) - mu * mu;
    float r   = rsqrtf(var + 1e-5f);
    float4 g4 = ((const float4*)gw)[tid];
    float4 b4 = ((const float4*)bw)[tid];
    float4 o;
    o.x = (v.x - mu) * r * g4.x + b4.x;
    o.y = (v.y - mu) * r * g4.y + b4.y;
    o.z = (v.z - mu) * r * g4.z + b4.z;
    o.w = (v.w - mu) * r * g4.w + b4.w;
    ((float4*)(Y + (size_t)row * E_DIM))[tid] = o;
}

// ---------------- TF32 tensor-core GEMM ----------------
// C(MxN) = A(MxK) @ B(KxN), fp32 in/out, tf32 mma.sync m16n8k8, fp32 accum.
// Block tile 128x256, BK=16, 256 threads = 8 warps (2 x 4), warp tile 64x64.
// EPI: 0 = none, 2 = bias+relu, 3 = bias+residual
template<int EPI>
__global__ __launch_bounds__(256, 1)
void gemm_tf32(const float* __restrict__ A, const float* __restrict__ Bm,
               const float* __restrict__ bias, const float* __restrict__ res,
               float* __restrict__ C, int M, int N, int K)
{
    // A as [m][k] (row stride 20 words -> conflict-free fragment loads)
    // B as [k][n] (row stride 260 words -> STS.128 writes, ~2-way reads)
    __shared__ unsigned As[128][20];
    __shared__ unsigned Bs[16][260];

    int tid  = threadIdx.x;
    int lane = tid & 31;
    int warp = tid >> 5;
    int wm   = warp >> 2;        // 0..1
    int wn   = warp & 3;         // 0..3
    int g    = lane >> 2;        // 0..7
    int t    = lane & 3;         // 0..3
    int bm   = blockIdx.y * 128;
    int bn   = blockIdx.x * 256;

    float acc[4][8][4];
    #pragma unroll
    for (int mt = 0; mt < 4; mt++)
        #pragma unroll
        for (int nt = 0; nt < 8; nt++)
            #pragma unroll
            for (int e = 0; e < 4; e++) acc[mt][nt][e] = 0.f;

    // staging maps
    int ar = tid >> 2;            // A rows: ar, ar+64   (idx = tid + i*256)
    int ac = (tid & 3) * 4;       // A col quad within BK=16
    int br = tid >> 6;            // B rows: br + i*4
    int bc = (tid & 63) * 4;      // B col quad within BN=256

    float4 a_st[2], b_st[4];
    #pragma unroll
    for (int i = 0; i < 2; i++)
        a_st[i] = *(const float4*)(A + (size_t)(bm + ar + i * 64) * K + ac);
    #pragma unroll
    for (int i = 0; i < 4; i++)
        b_st[i] = *(const float4*)(Bm + (size_t)(br + i * 4) * N + bn + bc);

    for (int k0 = 0; k0 < K; k0 += 16) {
        // store staged tile (convert to tf32 bits)
        #pragma unroll
        for (int i = 0; i < 2; i++) {
            uint4 u;
            u.x = f2tf32(a_st[i].x); u.y = f2tf32(a_st[i].y);
            u.z = f2tf32(a_st[i].z); u.w = f2tf32(a_st[i].w);
            *(uint4*)&As[ar + i * 64][ac] = u;
        }
        #pragma unroll
        for (int i = 0; i < 4; i++) {
            uint4 u;
            u.x = f2tf32(b_st[i].x); u.y = f2tf32(b_st[i].y);
            u.z = f2tf32(b_st[i].z); u.w = f2tf32(b_st[i].w);
            *(uint4*)&Bs[br + i * 4][bc] = u;
        }
        __syncthreads();

        // prefetch next tile (overlaps with mma below)
        if (k0 + 16 < K) {
            #pragma unroll
            for (int i = 0; i < 2; i++)
                a_st[i] = *(const float4*)(A + (size_t)(bm + ar + i * 64) * K + k0 + 16 + ac);
            #pragma unroll
            for (int i = 0; i < 4; i++)
                b_st[i] = *(const float4*)(Bm + (size_t)(k0 + 16 + br + i * 4) * N + bn + bc);
        }

        #pragma unroll
        for (int ks = 0; ks < 2; ks++) {
            unsigned af[4][4], bf[8][2];
            #pragma unroll
            for (int mt = 0; mt < 4; mt++) {
                int m0 = wm * 64 + mt * 16 + g;
                af[mt][0] = As[m0    ][ks * 8 + t];
                af[mt][1] = As[m0 + 8][ks * 8 + t];
                af[mt][2] = As[m0    ][ks * 8 + t + 4];
                af[mt][3] = As[m0 + 8][ks * 8 + t + 4];
            }
            #pragma unroll
            for (int nt = 0; nt < 8; nt++) {
                int n0 = wn * 64 + nt * 8 + g;
                bf[nt][0] = Bs[ks * 8 + t    ][n0];
                bf[nt][1] = Bs[ks * 8 + t + 4][n0];
            }
            #pragma unroll
            for (int mt = 0; mt < 4; mt++)
                #pragma unroll
                for (int nt = 0; nt < 8; nt++)
                    asm volatile(
                        "mma.sync.aligned.m16n8k8.row.col.f32.tf32.tf32.f32 "
                        "{%0,%1,%2,%3}, {%4,%5,%6,%7}, {%8,%9}, {%0,%1,%2,%3};"
                        : "+f"(acc[mt][nt][0]), "+f"(acc[mt][nt][1]),
                          "+f"(acc[mt][nt][2]), "+f"(acc[mt][nt][3])
                        : "r"(af[mt][0]), "r"(af[mt][1]), "r"(af[mt][2]), "r"(af[mt][3]),
                          "r"(bf[nt][0]), "r"(bf[nt][1]));
        }
        __syncthreads();
    }

    // epilogue
    #pragma unroll
    for (int mt = 0; mt < 4; mt++) {
        int r0 = bm + wm * 64 + mt * 16 + g;
        int r1 = r0 + 8;
        #pragma unroll
        for (int nt = 0; nt < 8; nt++) {
            int col = bn + wn * 64 + nt * 8 + 2 * t;
            float2 v0 = make_float2(acc[mt][nt][0], acc[mt][nt][1]);
            float2 v1 = make_float2(acc[mt][nt][2], acc[mt][nt][3]);
            if (EPI >= 2) {
                float2 bb = *(const float2*)(bias + col);
                v0.x += bb.x; v0.y += bb.y;
                v1.x += bb.x; v1.y += bb.y;
            }
            if (EPI == 2) {
                v0.x = fmaxf(v0.x, 0.f); v0.y = fmaxf(v0.y, 0.f);
                v1.x = fmaxf(v1.x, 0.f); v1.y = fmaxf(v1.y, 0.f);
            }
            if (EPI == 3) {
                float2 r0v = *(const float2*)(res + (size_t)r0 * N + col);
                float2 r1v = *(const float2*)(res + (size_t)r1 * N + col);
                v0.x += r0v.x; v0.y += r0v.y;
                v1.x += r1v.x; v1.y += r1v.y;
            }
            *(float2*)(C + (size_t)r0 * N + col) = v0;
            *(float2*)(C + (size_t)r1 * N + col) = v1;
        }
    }
}

// ---------------- causal flash attention (fp32) ----------------
// block = 128 threads = 128 query rows for one (b,h). Key tiles of 32.
__global__ void attn_kernel(const float* __restrict__ Q, const float* __restrict__ K,
                            const float* __restrict__ V, float* __restrict__ O)
{
    __shared__ float Ks[32][64];
    __shared__ float Vs[32][64];
    __shared__ float Ps[32][128];
    int b = blockIdx.z, h = blockIdx.y;
    int q0 = blockIdx.x * 128;
    int tid = threadIdx.x;
    int qi = q0 + tid;

    const float* qp = Q + ((size_t)(b * T_DIM + qi)) * E_DIM + h * HD;
    float qreg[HD];
    #pragma unroll
    for (int d = 0; d < HD; d += 4) *(float4*)(qreg + d) = *(const float4*)(qp + d);

    float acc[HD];
    #pragma unroll
    for (int d = 0; d < HD; d++) acc[d] = 0.f;
    float m = -1e30f, l = 0.f;

    int ntiles = blockIdx.x * 4 + 4;   // keys up to q0+127 inclusive
    for (int t = 0; t < ntiles; t++) {
        int kt = t * 32;
        __syncthreads();
        for (int i = tid; i < 32 * 16; i += 128) {
            int r = i >> 4, c = (i & 15) << 2;
            size_t gidx = ((size_t)(b * T_DIM + kt + r)) * E_DIM + h * HD + c;
            *(float4*)&Ks[r][c] = *(const float4*)(K + gidx);
            *(float4*)&Vs[r][c] = *(const float4*)(V + gidx);
        }
        __syncthreads();

        float mt = m;
        int jmax = qi - kt;
        #pragma unroll 2
        for (int j = 0; j < 32; j++) {
            float s = 0.f;
            #pragma unroll
            for (int d = 0; d < HD; d += 4) {
                float4 k4 = *(const float4*)&Ks[j][d];
                s = fmaf(qreg[d + 0], k4.x, s);
                s = fmaf(qreg[d + 1], k4.y, s);
                s = fmaf(qreg[d + 2], k4.z, s);
                s = fmaf(qreg[d + 3], k4.w, s);
            }
            s *= 0.125f;                       // 1/sqrt(64)
            s = (j <= jmax) ? s : -1e30f;      // causal mask
            Ps[j][tid] = s;
            mt = fmaxf(mt, s);
        }

        float corr = __expf(m - mt);
        l *= corr;
        #pragma unroll
        for (int d = 0; d < HD; d++) acc[d] *= corr;

        #pragma unroll 2
        for (int j = 0; j < 32; j++) {
            float pj = __expf(Ps[j][tid] - mt);
            l += pj;
            #pragma unroll
            for (int d = 0; d < HD; d += 4) {
                float4 v4 = *(const float4*)&Vs[j][d];
                acc[d + 0] = fmaf(pj, v4.x, acc[d + 0]);
                acc[d + 1] = fmaf(pj, v4.y, acc[d + 1]);
                acc[d + 2] = fmaf(pj, v4.z, acc[d + 2]);
                acc[d + 3] = fmaf(pj, v4.w, acc[d + 3]);
            }
        }
        m = mt;
    }

    float inv = 1.0f / l;
    float* op = O + ((size_t)(b * T_DIM + qi)) * E_DIM + h * HD;
    #pragma unroll
    for (int d = 0; d < HD; d += 4) {
        float4 o;
        o.x = acc[d + 0] * inv; o.y = acc[d + 1] * inv;
        o.z = acc[d + 2] * inv; o.w = acc[d + 3] * inv;
        *(float4*)(op + d) = o;
    }
}

// ---------------- launch ----------------
extern "C" void kernel_launch(void* const* d_in, const int* in_sizes, int n_in,
                              void* d_out, int out_size)
{
    const float* x     = (const float*)d_in[0];
    const float* ln1_g = (const float*)d_in[1];
    const float* ln1_b = (const float*)d_in[2];
    const float* Wq    = (const float*)d_in[3];
    const float* Wk    = (const float*)d_in[4];
    const float* Wv    = (const float*)d_in[5];
    const float* Wo    = (const float*)d_in[6];
    const float* bo    = (const float*)d_in[7];
    const float* ln2_g = (const float*)d_in[8];
    const float* ln2_b = (const float*)d_in[9];
    const float* W1    = (const float*)d_in[10];
    const float* b1    = (const float*)d_in[11];
    const float* W2    = (const float*)d_in[12];
    const float* b2    = (const float*)d_in[13];
    float* out = (float*)d_out;

    float *xn1, *q, *k, *v, *att, *x2, *h2, *ff;
    cudaGetSymbolAddress((void**)&xn1, g_xn1);
    cudaGetSymbolAddress((void**)&q,   g_q);
    cudaGetSymbolAddress((void**)&k,   g_k);
    cudaGetSymbolAddress((void**)&v,   g_v);
    cudaGetSymbolAddress((void**)&att, g_att);
    cudaGetSymbolAddress((void**)&x2,  g_x2);
    cudaGetSymbolAddress((void**)&h2,  g_h2);
    cudaGetSymbolAddress((void**)&ff,  g_ff);

    dim3 gE(E_DIM / 256, NROWS / 128);    // (4, 32)
    dim3 gF(FF_DIM / 256, NROWS / 128);   // (16, 32)

    ln_kernel<<<NROWS, 256>>>(x, ln1_g, ln1_b, xn1);
    gemm_tf32<0><<<gE, 256>>>(xn1, Wq, nullptr, nullptr, q, NROWS, E_DIM, E_DIM);
    gemm_tf32<0><<<gE, 256>>>(xn1, Wk, nullptr, nullptr, k, NROWS, E_DIM, E_DIM);
    gemm_tf32<0><<<gE, 256>>>(xn1, Wv, nullptr, nullptr, v, NROWS, E_DIM, E_DIM);
    attn_kernel<<<dim3(T_DIM / 128, HEADS, B_DIM), 128>>>(q, k, v, att);
    gemm_tf32<3><<<gE, 256>>>(att, Wo, bo, x, x2, NROWS, E_DIM, E_DIM);
    ln_kernel<<<NROWS, 256>>>(x2, ln2_g, ln2_b, h2);
    gemm_tf32<2><<<gF, 256>>>(h2, W1, b1, nullptr, ff, NROWS, FF_DIM, E_DIM);
    gemm_tf32<3><<<gE, 256>>>(ff, W2, b2, x2, out, NROWS, E_DIM, FF_DIM);
}

// round 5
// speedup vs baseline: 2.7113x; 1.4970x over previous
#include <cuda_runtime.h>

#define B_DIM   2
#define T_DIM   2048
#define E_DIM   1024
#define HEADS   16
#define HD      64
#define NROWS   (B_DIM * T_DIM)   // 4096
#define FF_DIM  (4 * E_DIM)       // 4096

// ---------------- scratch (no allocations allowed) ----------------
__device__ float g_xn1[NROWS * E_DIM];
__device__ float g_q  [NROWS * E_DIM];
__device__ float g_k  [NROWS * E_DIM];
__device__ float g_v  [NROWS * E_DIM];
__device__ float g_att[NROWS * E_DIM];
__device__ float g_x2 [NROWS * E_DIM];
__device__ float g_h2 [NROWS * E_DIM];
__device__ float g_ff [NROWS * FF_DIM];

__device__ __forceinline__ unsigned f2tf32(float x) {
    unsigned u;
    asm("cvt.rna.tf32.f32 %0, %1;" : "=r"(u) : "f"(x));
    return u;
}

__device__ __forceinline__ void mma_tf32(float* c, unsigned a0, unsigned a1,
                                         unsigned a2, unsigned a3,
                                         unsigned b0, unsigned b1)
{
    asm volatile(
        "mma.sync.aligned.m16n8k8.row.col.f32.tf32.tf32.f32 "
        "{%0,%1,%2,%3}, {%4,%5,%6,%7}, {%8,%9}, {%0,%1,%2,%3};"
        : "+f"(c[0]), "+f"(c[1]), "+f"(c[2]), "+f"(c[3])
        : "r"(a0), "r"(a1), "r"(a2), "r"(a3), "r"(b0), "r"(b1));
}

// ---------------- LayerNorm: one block per row ----------------
__global__ void ln_kernel(const float* __restrict__ X,
                          const float* __restrict__ gw,
                          const float* __restrict__ bw,
                          float* __restrict__ Y)
{
    int row = blockIdx.x;
    int tid = threadIdx.x;                 // 256 threads, 4 floats each
    const float4* x4 = (const float4*)(X + (size_t)row * E_DIM);
    float4 v = x4[tid];
    float s  = v.x + v.y + v.z + v.w;
    float s2 = v.x*v.x + v.y*v.y + v.z*v.z + v.w*v.w;
    #pragma unroll
    for (int o = 16; o > 0; o >>= 1) {
        s  += __shfl_xor_sync(0xffffffffu, s,  o);
        s2 += __shfl_xor_sync(0xffffffffu, s2, o);
    }
    __shared__ float ss[8], ss2[8];
    int w = tid >> 5;
    if ((tid & 31) == 0) { ss[w] = s; ss2[w] = s2; }
    __syncthreads();
    if (w == 0) {
        s  = ss [tid & 7];
        s2 = ss2[tid & 7];
        #pragma unroll
        for (int o = 4; o > 0; o >>= 1) {
            s  += __shfl_xor_sync(0xffffffffu, s,  o);
            s2 += __shfl_xor_sync(0xffffffffu, s2, o);
        }
        if (tid == 0) { ss[0] = s; ss2[0] = s2; }
    }
    __syncthreads();
    float mu  = ss[0]  * (1.0f / E_DIM);
    float var = ss2[0] * (1.0f / E_DIM) - mu * mu;
    float r   = rsqrtf(var + 1e-5f);
    float4 g4 = ((const float4*)gw)[tid];
    float4 b4 = ((const float4*)bw)[tid];
    float4 o;
    o.x = (v.x - mu) * r * g4.x + b4.x;
    o.y = (v.y - mu) * r * g4.y + b4.y;
    o.z = (v.z - mu) * r * g4.z + b4.z;
    o.w = (v.w - mu) * r * g4.w + b4.w;
    ((float4*)(Y + (size_t)row * E_DIM))[tid] = o;
}

// ---------------- TF32 tensor-core GEMM ----------------
// C(MxN) = A(MxK) @ B(KxN), fp32 in/out, tf32 mma.sync m16n8k8, fp32 accum.
// Block tile 128x256, BK=16, 256 threads = 8 warps (2 x 4), warp tile 64x64.
// EPI: 0 = none, 2 = bias+relu, 3 = bias+residual
template<int EPI>
__global__ __launch_bounds__(256, 1)
void gemm_tf32(const float* __restrict__ A, const float* __restrict__ Bm,
               const float* __restrict__ bias, const float* __restrict__ res,
               float* __restrict__ C, int M, int N, int K)
{
    __shared__ unsigned As[128][20];
    __shared__ unsigned Bs[16][260];

    int tid  = threadIdx.x;
    int lane = tid & 31;
    int warp = tid >> 5;
    int wm   = warp >> 2;        // 0..1
    int wn   = warp & 3;         // 0..3
    int g    = lane >> 2;        // 0..7
    int t    = lane & 3;         // 0..3
    int bm   = blockIdx.y * 128;
    int bn   = blockIdx.x * 256;

    float acc[4][8][4];
    #pragma unroll
    for (int mt = 0; mt < 4; mt++)
        #pragma unroll
        for (int nt = 0; nt < 8; nt++)
            #pragma unroll
            for (int e = 0; e < 4; e++) acc[mt][nt][e] = 0.f;

    int ar = tid >> 2;            // A rows: ar, ar+64
    int ac = (tid & 3) * 4;       // A col quad within BK=16
    int br = tid >> 6;            // B rows: br + i*4
    int bc = (tid & 63) * 4;      // B col quad within BN=256

    float4 a_st[2], b_st[4];
    #pragma unroll
    for (int i = 0; i < 2; i++)
        a_st[i] = *(const float4*)(A + (size_t)(bm + ar + i * 64) * K + ac);
    #pragma unroll
    for (int i = 0; i < 4; i++)
        b_st[i] = *(const float4*)(Bm + (size_t)(br + i * 4) * N + bn + bc);

    for (int k0 = 0; k0 < K; k0 += 16) {
        #pragma unroll
        for (int i = 0; i < 2; i++) {
            uint4 u;
            u.x = f2tf32(a_st[i].x); u.y = f2tf32(a_st[i].y);
            u.z = f2tf32(a_st[i].z); u.w = f2tf32(a_st[i].w);
            *(uint4*)&As[ar + i * 64][ac] = u;
        }
        #pragma unroll
        for (int i = 0; i < 4; i++) {
            uint4 u;
            u.x = f2tf32(b_st[i].x); u.y = f2tf32(b_st[i].y);
            u.z = f2tf32(b_st[i].z); u.w = f2tf32(b_st[i].w);
            *(uint4*)&Bs[br + i * 4][bc] = u;
        }
        __syncthreads();

        if (k0 + 16 < K) {
            #pragma unroll
            for (int i = 0; i < 2; i++)
                a_st[i] = *(const float4*)(A + (size_t)(bm + ar + i * 64) * K + k0 + 16 + ac);
            #pragma unroll
            for (int i = 0; i < 4; i++)
                b_st[i] = *(const float4*)(Bm + (size_t)(k0 + 16 + br + i * 4) * N + bn + bc);
        }

        #pragma unroll
        for (int ks = 0; ks < 2; ks++) {
            unsigned af[4][4], bf[8][2];
            #pragma unroll
            for (int mt = 0; mt < 4; mt++) {
                int m0 = wm * 64 + mt * 16 + g;
                af[mt][0] = As[m0    ][ks * 8 + t];
                af[mt][1] = As[m0 + 8][ks * 8 + t];
                af[mt][2] = As[m0    ][ks * 8 + t + 4];
                af[mt][3] = As[m0 + 8][ks * 8 + t + 4];
            }
            #pragma unroll
            for (int nt = 0; nt < 8; nt++) {
                int n0 = wn * 64 + nt * 8 + g;
                bf[nt][0] = Bs[ks * 8 + t    ][n0];
                bf[nt][1] = Bs[ks * 8 + t + 4][n0];
            }
            #pragma unroll
            for (int mt = 0; mt < 4; mt++)
                #pragma unroll
                for (int nt = 0; nt < 8; nt++)
                    mma_tf32(acc[mt][nt], af[mt][0], af[mt][1], af[mt][2], af[mt][3],
                             bf[nt][0], bf[nt][1]);
        }
        __syncthreads();
    }

    #pragma unroll
    for (int mt = 0; mt < 4; mt++) {
        int r0 = bm + wm * 64 + mt * 16 + g;
        int r1 = r0 + 8;
        #pragma unroll
        for (int nt = 0; nt < 8; nt++) {
            int col = bn + wn * 64 + nt * 8 + 2 * t;
            float2 v0 = make_float2(acc[mt][nt][0], acc[mt][nt][1]);
            float2 v1 = make_float2(acc[mt][nt][2], acc[mt][nt][3]);
            if (EPI >= 2) {
                float2 bb = *(const float2*)(bias + col);
                v0.x += bb.x; v0.y += bb.y;
                v1.x += bb.x; v1.y += bb.y;
            }
            if (EPI == 2) {
                v0.x = fmaxf(v0.x, 0.f); v0.y = fmaxf(v0.y, 0.f);
                v1.x = fmaxf(v1.x, 0.f); v1.y = fmaxf(v1.y, 0.f);
            }
            if (EPI == 3) {
                float2 r0v = *(const float2*)(res + (size_t)r0 * N + col);
                float2 r1v = *(const float2*)(res + (size_t)r1 * N + col);
                v0.x += r0v.x; v0.y += r0v.y;
                v1.x += r1v.x; v1.y += r1v.y;
            }
            *(float2*)(C + (size_t)r0 * N + col) = v0;
            *(float2*)(C + (size_t)r1 * N + col) = v1;
        }
    }
}

// ---------------- tensor-core causal flash attention (tf32) ----------------
// 256 threads = 8 warps; block = 128 q rows of one (b,h); warp w owns rows
// [w*16, w*16+16). KV tiles of 64. S = Q@K^T and O += P@V via m16n8k8 tf32.
#define APAD 68
__global__ __launch_bounds__(256)
void attn_tc(const float* __restrict__ Q, const float* __restrict__ K,
             const float* __restrict__ V, float* __restrict__ O)
{
    extern __shared__ unsigned sm[];
    unsigned* Qs = sm;                       // [128][APAD]  q rows x d
    unsigned* Ks = Qs + 128 * APAD;          // [64][APAD]   TRANSPOSED: [d][kv]
    unsigned* Vs = Ks + 64 * APAD;           // [64][APAD]   [kv][d]
    unsigned* Ps = Vs + 64 * APAD;           // [128][APAD]  q rows x kv

    int b = blockIdx.z, h = blockIdx.y;
    int q0 = blockIdx.x * 128;
    int tid  = threadIdx.x;
    int lane = tid & 31;
    int warp = tid >> 5;
    int g    = lane >> 2;
    int t    = lane & 3;
    int w16  = warp * 16;

    // ---- load Q tile (128 x 64) ----
    #pragma unroll
    for (int it = 0; it < 8; it++) {
        int i = tid + it * 256;              // 0..2047 float4 index
        int row = i >> 4, c4 = (i & 15) * 4;
        float4 qv = *(const float4*)(Q + ((size_t)(b * T_DIM + q0 + row)) * E_DIM + h * HD + c4);
        uint4 u;
        u.x = f2tf32(qv.x); u.y = f2tf32(qv.y);
        u.z = f2tf32(qv.z); u.w = f2tf32(qv.w);
        *(uint4*)&Qs[row * APAD + c4] = u;
    }

    float oc[8][4];
    #pragma unroll
    for (int nt = 0; nt < 8; nt++)
        #pragma unroll
        for (int e = 0; e < 4; e++) oc[nt][e] = 0.f;
    float m0 = -1e30f, m1 = -1e30f, l0 = 0.f, l1 = 0.f;

    int r0g = q0 + w16 + g;       // this thread's first row (global)
    int r1g = r0g + 8;

    int kvr = tid & 63;
    int d0  = (tid >> 6) * 16;

    int kend = q0 + 128;
    for (int kt = 0; kt < kend; kt += 64) {
        __syncthreads();          // prev iteration fully consumed Ks/Vs
        // ---- load K (transposed) and V tiles ----
        {
            const float* kp = K + ((size_t)(b * T_DIM + kt + kvr)) * E_DIM + h * HD + d0;
            const float* vp = V + ((size_t)(b * T_DIM + kt + kvr)) * E_DIM + h * HD + d0;
            float4 kv4[4], vv4[4];
            #pragma unroll
            for (int j = 0; j < 4; j++) {
                kv4[j] = *(const float4*)(kp + j * 4);
                vv4[j] = *(const float4*)(vp + j * 4);
            }
            #pragma unroll
            for (int j = 0; j < 4; j++) {
                const float* kf = (const float*)&kv4[j];
                #pragma unroll
                for (int e = 0; e < 4; e++)
                    Ks[(d0 + j * 4 + e) * APAD + kvr] = f2tf32(kf[e]);
                uint4 u;
                u.x = f2tf32(vv4[j].x); u.y = f2tf32(vv4[j].y);
                u.z = f2tf32(vv4[j].z); u.w = f2tf32(vv4[j].w);
                *(uint4*)&Vs[kvr * APAD + d0 + j * 4] = u;
            }
        }
        __syncthreads();

        // ---- S = Q @ K^T (warp's 16 rows x 64 kv) ----
        float sc[8][4];
        #pragma unroll
        for (int nt = 0; nt < 8; nt++)
            #pragma unroll
            for (int e = 0; e < 4; e++) sc[nt][e] = 0.f;

        #pragma unroll
        for (int ks = 0; ks < 8; ks++) {
            unsigned a0 = Qs[(w16 + g    ) * APAD + ks * 8 + t];
            unsigned a1 = Qs[(w16 + g + 8) * APAD + ks * 8 + t];
            unsigned a2 = Qs[(w16 + g    ) * APAD + ks * 8 + t + 4];
            unsigned a3 = Qs[(w16 + g + 8) * APAD + ks * 8 + t + 4];
            #pragma unroll
            for (int nt = 0; nt < 8; nt++) {
                unsigned b0 = Ks[(ks * 8 + t    ) * APAD + nt * 8 + g];
                unsigned b1 = Ks[(ks * 8 + t + 4) * APAD + nt * 8 + g];
                mma_tf32(sc[nt], a0, a1, a2, a3, b0, b1);
            }
        }

        // ---- scale + causal mask ----
        bool need_mask = (kt + 64 > q0);
        float tm0 = -1e30f, tm1 = -1e30f;
        #pragma unroll
        for (int nt = 0; nt < 8; nt++) {
            int c0 = kt + nt * 8 + 2 * t;
            #pragma unroll
            for (int e = 0; e < 4; e++) {
                float s = sc[nt][e] * 0.125f;
                if (need_mask) {
                    int col = c0 + (e & 1);
                    int row = (e < 2) ? r0g : r1g;
                    if (col > row) s = -1e30f;
                }
                sc[nt][e] = s;
            }
            tm0 = fmaxf(tm0, fmaxf(sc[nt][0], sc[nt][1]));
            tm1 = fmaxf(tm1, fmaxf(sc[nt][2], sc[nt][3]));
        }
        tm0 = fmaxf(tm0, __shfl_xor_sync(0xffffffffu, tm0, 1));
        tm0 = fmaxf(tm0, __shfl_xor_sync(0xffffffffu, tm0, 2));
        tm1 = fmaxf(tm1, __shfl_xor_sync(0xffffffffu, tm1, 1));
        tm1 = fmaxf(tm1, __shfl_xor_sync(0xffffffffu, tm1, 2));

        float mn0 = fmaxf(m0, tm0), mn1 = fmaxf(m1, tm1);
        float al0 = __expf(m0 - mn0), al1 = __expf(m1 - mn1);
        m0 = mn0; m1 = mn1;
        l0 *= al0; l1 *= al1;
        #pragma unroll
        for (int nt = 0; nt < 8; nt++) {
            oc[nt][0] *= al0; oc[nt][1] *= al0;
            oc[nt][2] *= al1; oc[nt][3] *= al1;
        }

        // ---- p = exp(s - m); stage P in smem (warp-private rows) ----
        float ps0 = 0.f, ps1 = 0.f;
        #pragma unroll
        for (int nt = 0; nt < 8; nt++) {
            float p0 = __expf(sc[nt][0] - mn0);
            float p1 = __expf(sc[nt][1] - mn0);
            float p2 = __expf(sc[nt][2] - mn1);
            float p3 = __expf(sc[nt][3] - mn1);
            ps0 += p0 + p1; ps1 += p2 + p3;
            int c0 = nt * 8 + 2 * t;
            Ps[(w16 + g    ) * APAD + c0    ] = f2tf32(p0);
            Ps[(w16 + g    ) * APAD + c0 + 1] = f2tf32(p1);
            Ps[(w16 + g + 8) * APAD + c0    ] = f2tf32(p2);
            Ps[(w16 + g + 8) * APAD + c0 + 1] = f2tf32(p3);
        }
        ps0 += __shfl_xor_sync(0xffffffffu, ps0, 1);
        ps0 += __shfl_xor_sync(0xffffffffu, ps0, 2);
        ps1 += __shfl_xor_sync(0xffffffffu, ps1, 1);
        ps1 += __shfl_xor_sync(0xffffffffu, ps1, 2);
        l0 += ps0; l1 += ps1;
        __syncwarp();

        // ---- O += P @ V ----
        #pragma unroll
        for (int ks = 0; ks < 8; ks++) {
            unsigned a0 = Ps[(w16 + g    ) * APAD + ks * 8 + t];
            unsigned a1 = Ps[(w16 + g + 8) * APAD + ks * 8 + t];
            unsigned a2 = Ps[(w16 + g    ) * APAD + ks * 8 + t + 4];
            unsigned a3 = Ps[(w16 + g + 8) * APAD + ks * 8 + t + 4];
            #pragma unroll
            for (int nt = 0; nt < 8; nt++) {
                unsigned b0 = Vs[(ks * 8 + t    ) * APAD + nt * 8 + g];
                unsigned b1 = Vs[(ks * 8 + t + 4) * APAD + nt * 8 + g];
                mma_tf32(oc[nt], a0, a1, a2, a3, b0, b1);
            }
        }
    }

    // ---- finalize: O /= l; write ----
    float inv0 = 1.0f / l0, inv1 = 1.0f / l1;
    #pragma unroll
    for (int nt = 0; nt < 8; nt++) {
        int col = h * HD + nt * 8 + 2 * t;
        float2 v0 = make_float2(oc[nt][0] * inv0, oc[nt][1] * inv0);
        float2 v1 = make_float2(oc[nt][2] * inv1, oc[nt][3] * inv1);
        *(float2*)(O + ((size_t)(b * T_DIM + r0g)) * E_DIM + col) = v0;
        *(float2*)(O + ((size_t)(b * T_DIM + r1g)) * E_DIM + col) = v1;
    }
}

#define ATT_SMEM ((128 * APAD + 64 * APAD + 64 * APAD + 128 * APAD) * 4)

// ---------------- launch ----------------
extern "C" void kernel_launch(void* const* d_in, const int* in_sizes, int n_in,
                              void* d_out, int out_size)
{
    const float* x     = (const float*)d_in[0];
    const float* ln1_g = (const float*)d_in[1];
    const float* ln1_b = (const float*)d_in[2];
    const float* Wq    = (const float*)d_in[3];
    const float* Wk    = (const float*)d_in[4];
    const float* Wv    = (const float*)d_in[5];
    const float* Wo    = (const float*)d_in[6];
    const float* bo    = (const float*)d_in[7];
    const float* ln2_g = (const float*)d_in[8];
    const float* ln2_b = (const float*)d_in[9];
    const float* W1    = (const float*)d_in[10];
    const float* b1    = (const float*)d_in[11];
    const float* W2    = (const float*)d_in[12];
    const float* b2    = (const float*)d_in[13];
    float* out = (float*)d_out;

    float *xn1, *q, *k, *v, *att, *x2, *h2, *ff;
    cudaGetSymbolAddress((void**)&xn1, g_xn1);
    cudaGetSymbolAddress((void**)&q,   g_q);
    cudaGetSymbolAddress((void**)&k,   g_k);
    cudaGetSymbolAddress((void**)&v,   g_v);
    cudaGetSymbolAddress((void**)&att, g_att);
    cudaGetSymbolAddress((void**)&x2,  g_x2);
    cudaGetSymbolAddress((void**)&h2,  g_h2);
    cudaGetSymbolAddress((void**)&ff,  g_ff);

    static int att_cfg = 0;
    if (!att_cfg) {
        cudaFuncSetAttribute(attn_tc, cudaFuncAttributeMaxDynamicSharedMemorySize, ATT_SMEM);
        att_cfg = 1;
    }

    dim3 gE(E_DIM / 256, NROWS / 128);    // (4, 32)
    dim3 gF(FF_DIM / 256, NROWS / 128);   // (16, 32)

    ln_kernel<<<NROWS, 256>>>(x, ln1_g, ln1_b, xn1);
    gemm_tf32<0><<<gE, 256>>>(xn1, Wq, nullptr, nullptr, q, NROWS, E_DIM, E_DIM);
    gemm_tf32<0><<<gE, 256>>>(xn1, Wk, nullptr, nullptr, k, NROWS, E_DIM, E_DIM);
    gemm_tf32<0><<<gE, 256>>>(xn1, Wv, nullptr, nullptr, v, NROWS, E_DIM, E_DIM);
    attn_tc<<<dim3(T_DIM / 128, HEADS, B_DIM), 256, ATT_SMEM>>>(q, k, v, att);
    gemm_tf32<3><<<gE, 256>>>(att, Wo, bo, x, x2, NROWS, E_DIM, E_DIM);
    ln_kernel<<<NROWS, 256>>>(x2, ln2_g, ln2_b, h2);
    gemm_tf32<2><<<gF, 256>>>(h2, W1, b1, nullptr, ff, NROWS, FF_DIM, E_DIM);
    gemm_tf32<3><<<gE, 256>>>(ff, W2, b2, x2, out, NROWS, E_DIM, FF_DIM);
}

// round 6
// speedup vs baseline: 3.0020x; 1.1072x over previous
#include <cuda_runtime.h>

#define B_DIM   2
#define T_DIM   2048
#define E_DIM   1024
#define HEADS   16
#define HD      64
#define NROWS   (B_DIM * T_DIM)   // 4096
#define FF_DIM  (4 * E_DIM)       // 4096

// ---------------- scratch (no allocations allowed) ----------------
__device__ float g_xn1[NROWS * E_DIM];
__device__ float g_q  [NROWS * E_DIM];
__device__ float g_k  [NROWS * E_DIM];
__device__ float g_v  [NROWS * E_DIM];
__device__ float g_att[NROWS * E_DIM];
__device__ float g_x2 [NROWS * E_DIM];
__device__ float g_h2 [NROWS * E_DIM];
__device__ float g_ff [NROWS * FF_DIM];

__device__ __forceinline__ unsigned f2tf32(float x) {
    unsigned u;
    asm("cvt.rna.tf32.f32 %0, %1;" : "=r"(u) : "f"(x));
    return u;
}

__device__ __forceinline__ void mma_tf32(float* c, unsigned a0, unsigned a1,
                                         unsigned a2, unsigned a3,
                                         unsigned b0, unsigned b1)
{
    asm volatile(
        "mma.sync.aligned.m16n8k8.row.col.f32.tf32.tf32.f32 "
        "{%0,%1,%2,%3}, {%4,%5,%6,%7}, {%8,%9}, {%0,%1,%2,%3};"
        : "+f"(c[0]), "+f"(c[1]), "+f"(c[2]), "+f"(c[3])
        : "r"(a0), "r"(a1), "r"(a2), "r"(a3), "r"(b0), "r"(b1));
}

__device__ __forceinline__ void cp_async16(void* smem_dst, const void* gmem_src) {
    unsigned s = (unsigned)__cvta_generic_to_shared(smem_dst);
    asm volatile("cp.async.cg.shared.global [%0], [%1], 16;" :: "r"(s), "l"(gmem_src));
}
#define CP_COMMIT()  asm volatile("cp.async.commit_group;" ::: "memory")
#define CP_WAIT1()   asm volatile("cp.async.wait_group 1;" ::: "memory")

// ---------------- LayerNorm: one block per row ----------------
__global__ void ln_kernel(const float* __restrict__ X,
                          const float* __restrict__ gw,
                          const float* __restrict__ bw,
                          float* __restrict__ Y)
{
    int row = blockIdx.x;
    int tid = threadIdx.x;                 // 256 threads, 4 floats each
    const float4* x4 = (const float4*)(X + (size_t)row * E_DIM);
    float4 v = x4[tid];
    float s  = v.x + v.y + v.z + v.w;
    float s2 = v.x*v.x + v.y*v.y + v.z*v.z + v.w*v.w;
    #pragma unroll
    for (int o = 16; o > 0; o >>= 1) {
        s  += __shfl_xor_sync(0xffffffffu, s,  o);
        s2 += __shfl_xor_sync(0xffffffffu, s2, o);
    }
    __shared__ float ss[8], ss2[8];
    int w = tid >> 5;
    if ((tid & 31) == 0) { ss[w] = s; ss2[w] = s2; }
    __syncthreads();
    if (w == 0) {
        s  = ss [tid & 7];
        s2 = ss2[tid & 7];
        #pragma unroll
        for (int o = 4; o > 0; o >>= 1) {
            s  += __shfl_xor_sync(0xffffffffu, s,  o);
            s2 += __shfl_xor_sync(0xffffffffu, s2, o);
        }
        if (tid == 0) { ss[0] = s; ss2[0] = s2; }
    }
    __syncthreads();
    float mu  = ss[0]  * (1.0f / E_DIM);
    float var = ss2[0] * (1.0f / E_DIM) - mu * mu;
    float r   = rsqrtf(var + 1e-5f);
    float4 g4 = ((const float4*)gw)[tid];
    float4 b4 = ((const float4*)bw)[tid];
    float4 o;
    o.x = (v.x - mu) * r * g4.x + b4.x;
    o.y = (v.y - mu) * r * g4.y + b4.y;
    o.z = (v.z - mu) * r * g4.z + b4.z;
    o.w = (v.w - mu) * r * g4.w + b4.w;
    ((float4*)(Y + (size_t)row * E_DIM))[tid] = o;
}

// ---------------- TF32 tensor-core GEMM (cp.async 3-stage pipeline) -------
// C(MxN) = A(MxK) @ B(KxN), fp32 in/out. Raw fp32 bits fed to tf32 mma
// (truncation semantics). Block tile 128x256, BK=16, 256 thr = 8 warps.
// EPI: 0 = none, 2 = bias+relu, 3 = bias+residual
#define STG_A (128 * 20)
#define STG_B (16 * 260)
#define GEMM_SMEM (3 * (STG_A + STG_B) * 4)

template<int EPI>
__device__ __forceinline__ void gemm_body(
    const float* __restrict__ A, const float* __restrict__ Bm,
    const float* __restrict__ bias, const float* __restrict__ res,
    float* __restrict__ C, int M, int N, int K, unsigned* sm)
{
    typedef unsigned (*AsT)[128][20];
    typedef unsigned (*BsT)[16][260];
    AsT As = (AsT)sm;
    BsT Bs = (BsT)(sm + 3 * STG_A);

    int tid  = threadIdx.x;
    int lane = tid & 31;
    int warp = tid >> 5;
    int wm   = warp >> 2;        // 0..1
    int wn   = warp & 3;         // 0..3
    int g    = lane >> 2;        // 0..7
    int t    = lane & 3;         // 0..3
    int bm   = blockIdx.y * 128;
    int bn   = blockIdx.x * 256;

    int ar = tid >> 2;            // A rows: ar, ar+64
    int ac = (tid & 3) * 4;       // A col quad within BK=16
    int br = tid >> 6;            // B rows: br + i*4
    int bc = (tid & 63) * 4;      // B col quad within BN=256

    float acc[4][8][4];
    #pragma unroll
    for (int mt = 0; mt < 4; mt++)
        #pragma unroll
        for (int nt = 0; nt < 8; nt++)
            #pragma unroll
            for (int e = 0; e < 4; e++) acc[mt][nt][e] = 0.f;

    const float* Abase = A + (size_t)(bm + ar) * K + ac;
    const float* Bbase = Bm + (size_t)br * N + bn + bc;
    size_t a64 = (size_t)64 * K;

    int NIT = K >> 4;

    // prologue: stages 0,1
    #pragma unroll
    for (int s = 0; s < 2; s++) {
        int k0 = s * 16;
        cp_async16(&As[s][ar][ac],      Abase + k0);
        cp_async16(&As[s][ar + 64][ac], Abase + k0 + a64);
        #pragma unroll
        for (int i = 0; i < 4; i++)
            cp_async16(&Bs[s][br + i * 4][bc], Bbase + (size_t)(k0 + i * 4) * N);
        CP_COMMIT();
    }

    for (int it = 0; it < NIT; it++) {
        CP_WAIT1();
        __syncthreads();

        int nf = it + 2;
        if (nf < NIT) {
            int sf = nf % 3;
            int k0 = nf * 16;
            cp_async16(&As[sf][ar][ac],      Abase + k0);
            cp_async16(&As[sf][ar + 64][ac], Abase + k0 + a64);
            #pragma unroll
            for (int i = 0; i < 4; i++)
                cp_async16(&Bs[sf][br + i * 4][bc], Bbase + (size_t)(k0 + i * 4) * N);
        }
        CP_COMMIT();

        int s = it % 3;
        #pragma unroll
        for (int ks = 0; ks < 2; ks++) {
            unsigned af[4][4], bf[8][2];
            #pragma unroll
            for (int mt = 0; mt < 4; mt++) {
                int m0 = wm * 64 + mt * 16 + g;
                af[mt][0] = As[s][m0    ][ks * 8 + t];
                af[mt][1] = As[s][m0 + 8][ks * 8 + t];
                af[mt][2] = As[s][m0    ][ks * 8 + t + 4];
                af[mt][3] = As[s][m0 + 8][ks * 8 + t + 4];
            }
            #pragma unroll
            for (int nt = 0; nt < 8; nt++) {
                int n0 = wn * 64 + nt * 8 + g;
                bf[nt][0] = Bs[s][ks * 8 + t    ][n0];
                bf[nt][1] = Bs[s][ks * 8 + t + 4][n0];
            }
            #pragma unroll
            for (int mt = 0; mt < 4; mt++)
                #pragma unroll
                for (int nt = 0; nt < 8; nt++)
                    mma_tf32(acc[mt][nt], af[mt][0], af[mt][1], af[mt][2], af[mt][3],
                             bf[nt][0], bf[nt][1]);
        }
    }

    #pragma unroll
    for (int mt = 0; mt < 4; mt++) {
        int r0 = bm + wm * 64 + mt * 16 + g;
        int r1 = r0 + 8;
        #pragma unroll
        for (int nt = 0; nt < 8; nt++) {
            int col = bn + wn * 64 + nt * 8 + 2 * t;
            float2 v0 = make_float2(acc[mt][nt][0], acc[mt][nt][1]);
            float2 v1 = make_float2(acc[mt][nt][2], acc[mt][nt][3]);
            if (EPI >= 2) {
                float2 bb = *(const float2*)(bias + col);
                v0.x += bb.x; v0.y += bb.y;
                v1.x += bb.x; v1.y += bb.y;
            }
            if (EPI == 2) {
                v0.x = fmaxf(v0.x, 0.f); v0.y = fmaxf(v0.y, 0.f);
                v1.x = fmaxf(v1.x, 0.f); v1.y = fmaxf(v1.y, 0.f);
            }
            if (EPI == 3) {
                float2 r0v = *(const float2*)(res + (size_t)r0 * N + col);
                float2 r1v = *(const float2*)(res + (size_t)r1 * N + col);
                v0.x += r0v.x; v0.y += r0v.y;
                v1.x += r1v.x; v1.y += r1v.y;
            }
            *(float2*)(C + (size_t)r0 * N + col) = v0;
            *(float2*)(C + (size_t)r1 * N + col) = v1;
        }
    }
}

template<int EPI>
__global__ __launch_bounds__(256, 1)
void gemm_tf32(const float* __restrict__ A, const float* __restrict__ Bm,
               const float* __restrict__ bias, const float* __restrict__ res,
               float* __restrict__ C, int M, int N, int K)
{
    extern __shared__ unsigned smg[];
    gemm_body<EPI>(A, Bm, bias, res, C, M, N, K, smg);
}

// fused QKV: blockIdx.z selects weight/output; shared A tiles hit L2.
__global__ __launch_bounds__(256, 1)
void gemm_qkv(const float* __restrict__ A,
              const float* __restrict__ B0, const float* __restrict__ B1,
              const float* __restrict__ B2,
              float* __restrict__ C0, float* __restrict__ C1, float* __restrict__ C2,
              int M, int N, int K)
{
    extern __shared__ unsigned smg[];
    const float* Bm = (blockIdx.z == 0) ? B0 : (blockIdx.z == 1) ? B1 : B2;
    float*       C  = (blockIdx.z == 0) ? C0 : (blockIdx.z == 1) ? C1 : C2;
    gemm_body<0>(A, Bm, nullptr, nullptr, C, M, N, K, smg);
}

// ---------------- tensor-core causal flash attention (tf32) ----------------
// 256 threads = 8 warps; block = 128 q rows of one (b,h); warp w owns rows
// [w*16, w*16+16). KV tiles of 64. S = Q@K^T and O += P@V via m16n8k8 tf32.
#define APAD 68
__global__ __launch_bounds__(256)
void attn_tc(const float* __restrict__ Q, const float* __restrict__ K,
             const float* __restrict__ V, float* __restrict__ O)
{
    extern __shared__ unsigned sm[];
    unsigned* Qs = sm;                       // [128][APAD]  q rows x d
    unsigned* Ks = Qs + 128 * APAD;          // [64][APAD]   TRANSPOSED: [d][kv]
    unsigned* Vs = Ks + 64 * APAD;           // [64][APAD]   [kv][d]
    unsigned* Ps = Vs + 64 * APAD;           // [128][APAD]  q rows x kv

    int b = blockIdx.z, h = blockIdx.y;
    int q0 = blockIdx.x * 128;
    int tid  = threadIdx.x;
    int lane = tid & 31;
    int warp = tid >> 5;
    int g    = lane >> 2;
    int t    = lane & 3;
    int w16  = warp * 16;

    #pragma unroll
    for (int it = 0; it < 8; it++) {
        int i = tid + it * 256;
        int row = i >> 4, c4 = (i & 15) * 4;
        float4 qv = *(const float4*)(Q + ((size_t)(b * T_DIM + q0 + row)) * E_DIM + h * HD + c4);
        uint4 u;
        u.x = f2tf32(qv.x); u.y = f2tf32(qv.y);
        u.z = f2tf32(qv.z); u.w = f2tf32(qv.w);
        *(uint4*)&Qs[row * APAD + c4] = u;
    }

    float oc[8][4];
    #pragma unroll
    for (int nt = 0; nt < 8; nt++)
        #pragma unroll
        for (int e = 0; e < 4; e++) oc[nt][e] = 0.f;
    float m0 = -1e30f, m1 = -1e30f, l0 = 0.f, l1 = 0.f;

    int r0g = q0 + w16 + g;
    int r1g = r0g + 8;

    int kvr = tid & 63;
    int d0  = (tid >> 6) * 16;

    int kend = q0 + 128;
    for (int kt = 0; kt < kend; kt += 64) {
        __syncthreads();
        {
            const float* kp = K + ((size_t)(b * T_DIM + kt + kvr)) * E_DIM + h * HD + d0;
            const float* vp = V + ((size_t)(b * T_DIM + kt + kvr)) * E_DIM + h * HD + d0;
            float4 kv4[4], vv4[4];
            #pragma unroll
            for (int j = 0; j < 4; j++) {
                kv4[j] = *(const float4*)(kp + j * 4);
                vv4[j] = *(const float4*)(vp + j * 4);
            }
            #pragma unroll
            for (int j = 0; j < 4; j++) {
                const float* kf = (const float*)&kv4[j];
                #pragma unroll
                for (int e = 0; e < 4; e++)
                    Ks[(d0 + j * 4 + e) * APAD + kvr] = f2tf32(kf[e]);
                uint4 u;
                u.x = f2tf32(vv4[j].x); u.y = f2tf32(vv4[j].y);
                u.z = f2tf32(vv4[j].z); u.w = f2tf32(vv4[j].w);
                *(uint4*)&Vs[kvr * APAD + d0 + j * 4] = u;
            }
        }
        __syncthreads();

        float sc[8][4];
        #pragma unroll
        for (int nt = 0; nt < 8; nt++)
            #pragma unroll
            for (int e = 0; e < 4; e++) sc[nt][e] = 0.f;

        #pragma unroll
        for (int ks = 0; ks < 8; ks++) {
            unsigned a0 = Qs[(w16 + g    ) * APAD + ks * 8 + t];
            unsigned a1 = Qs[(w16 + g + 8) * APAD + ks * 8 + t];
            unsigned a2 = Qs[(w16 + g    ) * APAD + ks * 8 + t + 4];
            unsigned a3 = Qs[(w16 + g + 8) * APAD + ks * 8 + t + 4];
            #pragma unroll
            for (int nt = 0; nt < 8; nt++) {
                unsigned b0 = Ks[(ks * 8 + t    ) * APAD + nt * 8 + g];
                unsigned b1 = Ks[(ks * 8 + t + 4) * APAD + nt * 8 + g];
                mma_tf32(sc[nt], a0, a1, a2, a3, b0, b1);
            }
        }

        bool need_mask = (kt + 64 > q0);
        float tm0 = -1e30f, tm1 = -1e30f;
        #pragma unroll
        for (int nt = 0; nt < 8; nt++) {
            int c0 = kt + nt * 8 + 2 * t;
            #pragma unroll
            for (int e = 0; e < 4; e++) {
                float s = sc[nt][e] * 0.125f;
                if (need_mask) {
                    int col = c0 + (e & 1);
                    int row = (e < 2) ? r0g : r1g;
                    if (col > row) s = -1e30f;
                }
                sc[nt][e] = s;
            }
            tm0 = fmaxf(tm0, fmaxf(sc[nt][0], sc[nt][1]));
            tm1 = fmaxf(tm1, fmaxf(sc[nt][2], sc[nt][3]));
        }
        tm0 = fmaxf(tm0, __shfl_xor_sync(0xffffffffu, tm0, 1));
        tm0 = fmaxf(tm0, __shfl_xor_sync(0xffffffffu, tm0, 2));
        tm1 = fmaxf(tm1, __shfl_xor_sync(0xffffffffu, tm1, 1));
        tm1 = fmaxf(tm1, __shfl_xor_sync(0xffffffffu, tm1, 2));

        float mn0 = fmaxf(m0, tm0), mn1 = fmaxf(m1, tm1);
        float al0 = __expf(m0 - mn0), al1 = __expf(m1 - mn1);
        m0 = mn0; m1 = mn1;
        l0 *= al0; l1 *= al1;
        #pragma unroll
        for (int nt = 0; nt < 8; nt++) {
            oc[nt][0] *= al0; oc[nt][1] *= al0;
            oc[nt][2] *= al1; oc[nt][3] *= al1;
        }

        float ps0 = 0.f, ps1 = 0.f;
        #pragma unroll
        for (int nt = 0; nt < 8; nt++) {
            float p0 = __expf(sc[nt][0] - mn0);
            float p1 = __expf(sc[nt][1] - mn0);
            float p2 = __expf(sc[nt][2] - mn1);
            float p3 = __expf(sc[nt][3] - mn1);
            ps0 += p0 + p1; ps1 += p2 + p3;
            int c0 = nt * 8 + 2 * t;
            Ps[(w16 + g    ) * APAD + c0    ] = f2tf32(p0);
            Ps[(w16 + g    ) * APAD + c0 + 1] = f2tf32(p1);
            Ps[(w16 + g + 8) * APAD + c0    ] = f2tf32(p2);
            Ps[(w16 + g + 8) * APAD + c0 + 1] = f2tf32(p3);
        }
        ps0 += __shfl_xor_sync(0xffffffffu, ps0, 1);
        ps0 += __shfl_xor_sync(0xffffffffu, ps0, 2);
        ps1 += __shfl_xor_sync(0xffffffffu, ps1, 1);
        ps1 += __shfl_xor_sync(0xffffffffu, ps1, 2);
        l0 += ps0; l1 += ps1;
        __syncwarp();

        #pragma unroll
        for (int ks = 0; ks < 8; ks++) {
            unsigned a0 = Ps[(w16 + g    ) * APAD + ks * 8 + t];
            unsigned a1 = Ps[(w16 + g + 8) * APAD + ks * 8 + t];
            unsigned a2 = Ps[(w16 + g    ) * APAD + ks * 8 + t + 4];
            unsigned a3 = Ps[(w16 + g + 8) * APAD + ks * 8 + t + 4];
            #pragma unroll
            for (int nt = 0; nt < 8; nt++) {
                unsigned b0 = Vs[(ks * 8 + t    ) * APAD + nt * 8 + g];
                unsigned b1 = Vs[(ks * 8 + t + 4) * APAD + nt * 8 + g];
                mma_tf32(oc[nt], a0, a1, a2, a3, b0, b1);
            }
        }
    }

    float inv0 = 1.0f / l0, inv1 = 1.0f / l1;
    #pragma unroll
    for (int nt = 0; nt < 8; nt++) {
        int col = h * HD + nt * 8 + 2 * t;
        float2 v0 = make_float2(oc[nt][0] * inv0, oc[nt][1] * inv0);
        float2 v1 = make_float2(oc[nt][2] * inv1, oc[nt][3] * inv1);
        *(float2*)(O + ((size_t)(b * T_DIM + r0g)) * E_DIM + col) = v0;
        *(float2*)(O + ((size_t)(b * T_DIM + r1g)) * E_DIM + col) = v1;
    }
}

#define ATT_SMEM ((128 * APAD + 64 * APAD + 64 * APAD + 128 * APAD) * 4)

// ---------------- launch ----------------
extern "C" void kernel_launch(void* const* d_in, const int* in_sizes, int n_in,
                              void* d_out, int out_size)
{
    const float* x     = (const float*)d_in[0];
    const float* ln1_g = (const float*)d_in[1];
    const float* ln1_b = (const float*)d_in[2];
    const float* Wq    = (const float*)d_in[3];
    const float* Wk    = (const float*)d_in[4];
    const float* Wv    = (const float*)d_in[5];
    const float* Wo    = (const float*)d_in[6];
    const float* bo    = (const float*)d_in[7];
    const float* ln2_g = (const float*)d_in[8];
    const float* ln2_b = (const float*)d_in[9];
    const float* W1    = (const float*)d_in[10];
    const float* b1    = (const float*)d_in[11];
    const float* W2    = (const float*)d_in[12];
    const float* b2    = (const float*)d_in[13];
    float* out = (float*)d_out;

    float *xn1, *q, *k, *v, *att, *x2, *h2, *ff;
    cudaGetSymbolAddress((void**)&xn1, g_xn1);
    cudaGetSymbolAddress((void**)&q,   g_q);
    cudaGetSymbolAddress((void**)&k,   g_k);
    cudaGetSymbolAddress((void**)&v,   g_v);
    cudaGetSymbolAddress((void**)&att, g_att);
    cudaGetSymbolAddress((void**)&x2,  g_x2);
    cudaGetSymbolAddress((void**)&h2,  g_h2);
    cudaGetSymbolAddress((void**)&ff,  g_ff);

    static int cfg = 0;
    if (!cfg) {
        cudaFuncSetAttribute(attn_tc, cudaFuncAttributeMaxDynamicSharedMemorySize, ATT_SMEM);
        cudaFuncSetAttribute(gemm_qkv, cudaFuncAttributeMaxDynamicSharedMemorySize, GEMM_SMEM);
        cudaFuncSetAttribute(gemm_tf32<2>, cudaFuncAttributeMaxDynamicSharedMemorySize, GEMM_SMEM);
        cudaFuncSetAttribute(gemm_tf32<3>, cudaFuncAttributeMaxDynamicSharedMemorySize, GEMM_SMEM);
        cfg = 1;
    }

    dim3 gE(E_DIM / 256, NROWS / 128);          // (4, 32)
    dim3 gQKV(E_DIM / 256, NROWS / 128, 3);     // (4, 32, 3)
    dim3 gF(FF_DIM / 256, NROWS / 128);         // (16, 32)

    ln_kernel<<<NROWS, 256>>>(x, ln1_g, ln1_b, xn1);
    gemm_qkv<<<gQKV, 256, GEMM_SMEM>>>(xn1, Wq, Wk, Wv, q, k, v, NROWS, E_DIM, E_DIM);
    attn_tc<<<dim3(T_DIM / 128, HEADS, B_DIM), 256, ATT_SMEM>>>(q, k, v, att);
    gemm_tf32<3><<<gE, 256, GEMM_SMEM>>>(att, Wo, bo, x, x2, NROWS, E_DIM, E_DIM);
    ln_kernel<<<NROWS, 256>>>(x2, ln2_g, ln2_b, h2);
    gemm_tf32<2><<<gF, 256, GEMM_SMEM>>>(h2, W1, b1, nullptr, ff, NROWS, FF_DIM, E_DIM);
    gemm_tf32<3><<<gE, 256, GEMM_SMEM>>>(ff, W2, b2, x2, out, NROWS, E_DIM, FF_DIM);
}

// round 7
// speedup vs baseline: 3.0412x; 1.0131x over previous
#include <cuda_runtime.h>

#define B_DIM   2
#define T_DIM   2048
#define E_DIM   1024
#define HEADS   16
#define HD      64
#define NROWS   (B_DIM * T_DIM)   // 4096
#define FF_DIM  (4 * E_DIM)       // 4096

// ---------------- scratch (no allocations allowed) ----------------
__device__ float g_xn1[NROWS * E_DIM];
__device__ float g_q  [NROWS * E_DIM];
__device__ float g_k  [NROWS * E_DIM];
__device__ float g_v  [NROWS * E_DIM];
__device__ float g_att[NROWS * E_DIM];
__device__ float g_x2 [NROWS * E_DIM];
__device__ float g_h2 [NROWS * E_DIM];
__device__ float g_ff [NROWS * FF_DIM];

__device__ __forceinline__ unsigned f2tf32(float x) {
    unsigned u;
    asm("cvt.rna.tf32.f32 %0, %1;" : "=r"(u) : "f"(x));
    return u;
}
// round fp32 value to tf32 grid, keep as fp32
__device__ __forceinline__ float rnd_tf32(float x) {
    return __uint_as_float(f2tf32(x));
}

__device__ __forceinline__ void mma_tf32(float* c, unsigned a0, unsigned a1,
                                         unsigned a2, unsigned a3,
                                         unsigned b0, unsigned b1)
{
    asm volatile(
        "mma.sync.aligned.m16n8k8.row.col.f32.tf32.tf32.f32 "
        "{%0,%1,%2,%3}, {%4,%5,%6,%7}, {%8,%9}, {%0,%1,%2,%3};"
        : "+f"(c[0]), "+f"(c[1]), "+f"(c[2]), "+f"(c[3])
        : "r"(a0), "r"(a1), "r"(a2), "r"(a3), "r"(b0), "r"(b1));
}

__device__ __forceinline__ void cp_async16(void* smem_dst, const void* gmem_src) {
    unsigned s = (unsigned)__cvta_generic_to_shared(smem_dst);
    asm volatile("cp.async.cg.shared.global [%0], [%1], 16;" :: "r"(s), "l"(gmem_src));
}
#define CP_COMMIT()  asm volatile("cp.async.commit_group;" ::: "memory")
#define CP_WAIT1()   asm volatile("cp.async.wait_group 1;" ::: "memory")

// ---------------- LayerNorm: one block per row (tf32-rounded output) ------
__global__ void ln_kernel(const float* __restrict__ X,
                          const float* __restrict__ gw,
                          const float* __restrict__ bw,
                          float* __restrict__ Y)
{
    int row = blockIdx.x;
    int tid = threadIdx.x;                 // 256 threads, 4 floats each
    const float4* x4 = (const float4*)(X + (size_t)row * E_DIM);
    float4 v = x4[tid];
    float s  = v.x + v.y + v.z + v.w;
    float s2 = v.x*v.x + v.y*v.y + v.z*v.z + v.w*v.w;
    #pragma unroll
    for (int o = 16; o > 0; o >>= 1) {
        s  += __shfl_xor_sync(0xffffffffu, s,  o);
        s2 += __shfl_xor_sync(0xffffffffu, s2, o);
    }
    __shared__ float ss[8], ss2[8];
    int w = tid >> 5;
    if ((tid & 31) == 0) { ss[w] = s; ss2[w] = s2; }
    __syncthreads();
    if (w == 0) {
        s  = ss [tid & 7];
        s2 = ss2[tid & 7];
        #pragma unroll
        for (int o = 4; o > 0; o >>= 1) {
            s  += __shfl_xor_sync(0xffffffffu, s,  o);
            s2 += __shfl_xor_sync(0xffffffffu, s2, o);
        }
        if (tid == 0) { ss[0] = s; ss2[0] = s2; }
    }
    __syncthreads();
    float mu  = ss[0]  * (1.0f / E_DIM);
    float var = ss2[0] * (1.0f / E_DIM) - mu * mu;
    float r   = rsqrtf(var + 1e-5f);
    float4 g4 = ((const float4*)gw)[tid];
    float4 b4 = ((const float4*)bw)[tid];
    float4 o;
    // output consumed ONLY as GEMM-A: pre-round to tf32 grid
    o.x = rnd_tf32((v.x - mu) * r * g4.x + b4.x);
    o.y = rnd_tf32((v.y - mu) * r * g4.y + b4.y);
    o.z = rnd_tf32((v.z - mu) * r * g4.z + b4.z);
    o.w = rnd_tf32((v.w - mu) * r * g4.w + b4.w);
    ((float4*)(Y + (size_t)row * E_DIM))[tid] = o;
}

// ---------------- TF32 tensor-core GEMM (cp.async 3-stage, 2 blocks/SM) ---
// C(MxN) = A(MxK) @ B(KxN), fp32 in/out. A pre-rounded to tf32 by producer
// (HW truncation lossless); B rounded at fragment load via +0x1000.
// Block tile 128x128, BK=16, 256 thr = 8 warps (2x4), warp tile 64x32.
// EPI: 0 = none, 2 = bias+relu (tf32-rounded out), 3 = bias+residual
#define STG_A (128 * 20)
#define STG_B (16 * 132)
#define GEMM_SMEM (3 * (STG_A + STG_B) * 4)

template<int EPI>
__device__ __forceinline__ void gemm_body(
    const float* __restrict__ A, const float* __restrict__ Bm,
    const float* __restrict__ bias, const float* __restrict__ res,
    float* __restrict__ C, int M, int N, int K, unsigned* sm)
{
    typedef unsigned (*AsT)[128][20];
    typedef unsigned (*BsT)[16][132];
    AsT As = (AsT)sm;
    BsT Bs = (BsT)(sm + 3 * STG_A);

    int tid  = threadIdx.x;
    int lane = tid & 31;
    int warp = tid >> 5;
    int wm   = warp >> 2;        // 0..1
    int wn   = warp & 3;         // 0..3
    int g    = lane >> 2;        // 0..7
    int t    = lane & 3;         // 0..3
    int bm   = blockIdx.y * 128;
    int bn   = blockIdx.x * 128;

    int ar = tid >> 2;            // A rows: ar, ar+64
    int ac = (tid & 3) * 4;       // A col quad within BK=16
    int br = tid >> 5;            // B rows: br, br+8
    int bc = (tid & 31) * 4;      // B col quad within BN=128

    float acc[4][4][4];
    #pragma unroll
    for (int mt = 0; mt < 4; mt++)
        #pragma unroll
        for (int nt = 0; nt < 4; nt++)
            #pragma unroll
            for (int e = 0; e < 4; e++) acc[mt][nt][e] = 0.f;

    const float* Abase = A + (size_t)(bm + ar) * K + ac;
    const float* Bbase = Bm + (size_t)br * N + bn + bc;
    size_t a64 = (size_t)64 * K;
    size_t b8  = (size_t)8 * N;

    int NIT = K >> 4;

    #pragma unroll
    for (int s = 0; s < 2; s++) {
        int k0 = s * 16;
        cp_async16(&As[s][ar][ac],      Abase + k0);
        cp_async16(&As[s][ar + 64][ac], Abase + k0 + a64);
        cp_async16(&Bs[s][br][bc],     Bbase + (size_t)k0 * N);
        cp_async16(&Bs[s][br + 8][bc], Bbase + (size_t)k0 * N + b8);
        CP_COMMIT();
    }

    for (int it = 0; it < NIT; it++) {
        CP_WAIT1();
        __syncthreads();

        int nf = it + 2;
        if (nf < NIT) {
            int sf = nf % 3;
            int k0 = nf * 16;
            cp_async16(&As[sf][ar][ac],      Abase + k0);
            cp_async16(&As[sf][ar + 64][ac], Abase + k0 + a64);
            cp_async16(&Bs[sf][br][bc],     Bbase + (size_t)k0 * N);
            cp_async16(&Bs[sf][br + 8][bc], Bbase + (size_t)k0 * N + b8);
        }
        CP_COMMIT();

        int s = it % 3;
        #pragma unroll
        for (int ks = 0; ks < 2; ks++) {
            unsigned af[4][4], bf[4][2];
            #pragma unroll
            for (int mt = 0; mt < 4; mt++) {
                int m0 = wm * 64 + mt * 16 + g;
                af[mt][0] = As[s][m0    ][ks * 8 + t];
                af[mt][1] = As[s][m0 + 8][ks * 8 + t];
                af[mt][2] = As[s][m0    ][ks * 8 + t + 4];
                af[mt][3] = As[s][m0 + 8][ks * 8 + t + 4];
            }
            #pragma unroll
            for (int nt = 0; nt < 4; nt++) {
                int n0 = wn * 32 + nt * 8 + g;
                // +0x1000: round-to-nearest on tf32 truncation boundary
                bf[nt][0] = Bs[s][ks * 8 + t    ][n0] + 0x1000u;
                bf[nt][1] = Bs[s][ks * 8 + t + 4][n0] + 0x1000u;
            }
            #pragma unroll
            for (int mt = 0; mt < 4; mt++)
                #pragma unroll
                for (int nt = 0; nt < 4; nt++)
                    mma_tf32(acc[mt][nt], af[mt][0], af[mt][1], af[mt][2], af[mt][3],
                             bf[nt][0], bf[nt][1]);
        }
    }

    #pragma unroll
    for (int mt = 0; mt < 4; mt++) {
        int r0 = bm + wm * 64 + mt * 16 + g;
        int r1 = r0 + 8;
        #pragma unroll
        for (int nt = 0; nt < 4; nt++) {
            int col = bn + wn * 32 + nt * 8 + 2 * t;
            float2 v0 = make_float2(acc[mt][nt][0], acc[mt][nt][1]);
            float2 v1 = make_float2(acc[mt][nt][2], acc[mt][nt][3]);
            if (EPI >= 2) {
                float2 bb = *(const float2*)(bias + col);
                v0.x += bb.x; v0.y += bb.y;
                v1.x += bb.x; v1.y += bb.y;
            }
            if (EPI == 2) {
                // output consumed only as GEMM-A: round to tf32 grid
                v0.x = rnd_tf32(fmaxf(v0.x, 0.f)); v0.y = rnd_tf32(fmaxf(v0.y, 0.f));
                v1.x = rnd_tf32(fmaxf(v1.x, 0.f)); v1.y = rnd_tf32(fmaxf(v1.y, 0.f));
            }
            if (EPI == 3) {
                float2 r0v = *(const float2*)(res + (size_t)r0 * N + col);
                float2 r1v = *(const float2*)(res + (size_t)r1 * N + col);
                v0.x += r0v.x; v0.y += r0v.y;
                v1.x += r1v.x; v1.y += r1v.y;
            }
            *(float2*)(C + (size_t)r0 * N + col) = v0;
            *(float2*)(C + (size_t)r1 * N + col) = v1;
        }
    }
}

template<int EPI>
__global__ __launch_bounds__(256, 2)
void gemm_tf32(const float* __restrict__ A, const float* __restrict__ Bm,
               const float* __restrict__ bias, const float* __restrict__ res,
               float* __restrict__ C, int M, int N, int K)
{
    extern __shared__ unsigned smg[];
    gemm_body<EPI>(A, Bm, bias, res, C, M, N, K, smg);
}

// fused QKV: blockIdx.z selects weight/output; shared A tiles hit L2.
__global__ __launch_bounds__(256, 2)
void gemm_qkv(const float* __restrict__ A,
              const float* __restrict__ B0, const float* __restrict__ B1,
              const float* __restrict__ B2,
              float* __restrict__ C0, float* __restrict__ C1, float* __restrict__ C2,
              int M, int N, int K)
{
    extern __shared__ unsigned smg[];
    const float* Bm = (blockIdx.z == 0) ? B0 : (blockIdx.z == 1) ? B1 : B2;
    float*       C  = (blockIdx.z == 0) ? C0 : (blockIdx.z == 1) ? C1 : C2;
    gemm_body<0>(A, Bm, nullptr, nullptr, C, M, N, K, smg);
}

// ---------------- tensor-core causal flash attention (tf32) ----------------
// 256 threads = 8 warps; block = 128 q rows of one (b,h); warp w owns rows
// [w*16, w*16+16). KV tiles of 64. S = Q@K^T and O += P@V via m16n8k8 tf32.
#define APAD 68
__global__ __launch_bounds__(256)
void attn_tc(const float* __restrict__ Q, const float* __restrict__ K,
             const float* __restrict__ V, float* __restrict__ O)
{
    extern __shared__ unsigned sm[];
    unsigned* Qs = sm;                       // [128][APAD]  q rows x d
    unsigned* Ks = Qs + 128 * APAD;          // [64][APAD]   TRANSPOSED: [d][kv]
    unsigned* Vs = Ks + 64 * APAD;           // [64][APAD]   [kv][d]
    unsigned* Ps = Vs + 64 * APAD;           // [128][APAD]  q rows x kv

    int b = blockIdx.z, h = blockIdx.y;
    int q0 = blockIdx.x * 128;
    int tid  = threadIdx.x;
    int lane = tid & 31;
    int warp = tid >> 5;
    int g    = lane >> 2;
    int t    = lane & 3;
    int w16  = warp * 16;

    #pragma unroll
    for (int it = 0; it < 8; it++) {
        int i = tid + it * 256;
        int row = i >> 4, c4 = (i & 15) * 4;
        float4 qv = *(const float4*)(Q + ((size_t)(b * T_DIM + q0 + row)) * E_DIM + h * HD + c4);
        uint4 u;
        u.x = f2tf32(qv.x); u.y = f2tf32(qv.y);
        u.z = f2tf32(qv.z); u.w = f2tf32(qv.w);
        *(uint4*)&Qs[row * APAD + c4] = u;
    }

    float oc[8][4];
    #pragma unroll
    for (int nt = 0; nt < 8; nt++)
        #pragma unroll
        for (int e = 0; e < 4; e++) oc[nt][e] = 0.f;
    float m0 = -1e30f, m1 = -1e30f, l0 = 0.f, l1 = 0.f;

    int r0g = q0 + w16 + g;
    int r1g = r0g + 8;

    int kvr = tid & 63;
    int d0  = (tid >> 6) * 16;

    int kend = q0 + 128;
    for (int kt = 0; kt < kend; kt += 64) {
        __syncthreads();
        {
            const float* kp = K + ((size_t)(b * T_DIM + kt + kvr)) * E_DIM + h * HD + d0;
            const float* vp = V + ((size_t)(b * T_DIM + kt + kvr)) * E_DIM + h * HD + d0;
            float4 kv4[4], vv4[4];
            #pragma unroll
            for (int j = 0; j < 4; j++) {
                kv4[j] = *(const float4*)(kp + j * 4);
                vv4[j] = *(const float4*)(vp + j * 4);
            }
            #pragma unroll
            for (int j = 0; j < 4; j++) {
                const float* kf = (const float*)&kv4[j];
                #pragma unroll
                for (int e = 0; e < 4; e++)
                    Ks[(d0 + j * 4 + e) * APAD + kvr] = f2tf32(kf[e]);
                uint4 u;
                u.x = f2tf32(vv4[j].x); u.y = f2tf32(vv4[j].y);
                u.z = f2tf32(vv4[j].z); u.w = f2tf32(vv4[j].w);
                *(uint4*)&Vs[kvr * APAD + d0 + j * 4] = u;
            }
        }
        __syncthreads();

        float sc[8][4];
        #pragma unroll
        for (int nt = 0; nt < 8; nt++)
            #pragma unroll
            for (int e = 0; e < 4; e++) sc[nt][e] = 0.f;

        #pragma unroll
        for (int ks = 0; ks < 8; ks++) {
            unsigned a0 = Qs[(w16 + g    ) * APAD + ks * 8 + t];
            unsigned a1 = Qs[(w16 + g + 8) * APAD + ks * 8 + t];
            unsigned a2 = Qs[(w16 + g    ) * APAD + ks * 8 + t + 4];
            unsigned a3 = Qs[(w16 + g + 8) * APAD + ks * 8 + t + 4];
            #pragma unroll
            for (int nt = 0; nt < 8; nt++) {
                unsigned b0 = Ks[(ks * 8 + t    ) * APAD + nt * 8 + g];
                unsigned b1 = Ks[(ks * 8 + t + 4) * APAD + nt * 8 + g];
                mma_tf32(sc[nt], a0, a1, a2, a3, b0, b1);
            }
        }

        bool need_mask = (kt + 64 > q0);
        float tm0 = -1e30f, tm1 = -1e30f;
        #pragma unroll
        for (int nt = 0; nt < 8; nt++) {
            int c0 = kt + nt * 8 + 2 * t;
            #pragma unroll
            for (int e = 0; e < 4; e++) {
                float s = sc[nt][e] * 0.125f;
                if (need_mask) {
                    int col = c0 + (e & 1);
                    int row = (e < 2) ? r0g : r1g;
                    if (col > row) s = -1e30f;
                }
                sc[nt][e] = s;
            }
            tm0 = fmaxf(tm0, fmaxf(sc[nt][0], sc[nt][1]));
            tm1 = fmaxf(tm1, fmaxf(sc[nt][2], sc[nt][3]));
        }
        tm0 = fmaxf(tm0, __shfl_xor_sync(0xffffffffu, tm0, 1));
        tm0 = fmaxf(tm0, __shfl_xor_sync(0xffffffffu, tm0, 2));
        tm1 = fmaxf(tm1, __shfl_xor_sync(0xffffffffu, tm1, 1));
        tm1 = fmaxf(tm1, __shfl_xor_sync(0xffffffffu, tm1, 2));

        float mn0 = fmaxf(m0, tm0), mn1 = fmaxf(m1, tm1);
        float al0 = __expf(m0 - mn0), al1 = __expf(m1 - mn1);
        m0 = mn0; m1 = mn1;
        l0 *= al0; l1 *= al1;
        #pragma unroll
        for (int nt = 0; nt < 8; nt++) {
            oc[nt][0] *= al0; oc[nt][1] *= al0;
            oc[nt][2] *= al1; oc[nt][3] *= al1;
        }

        float ps0 = 0.f, ps1 = 0.f;
        #pragma unroll
        for (int nt = 0; nt < 8; nt++) {
            float p0 = __expf(sc[nt][0] - mn0);
            float p1 = __expf(sc[nt][1] - mn0);
            float p2 = __expf(sc[nt][2] - mn1);
            float p3 = __expf(sc[nt][3] - mn1);
            ps0 += p0 + p1; ps1 += p2 + p3;
            int c0 = nt * 8 + 2 * t;
            Ps[(w16 + g    ) * APAD + c0    ] = f2tf32(p0);
            Ps[(w16 + g    ) * APAD + c0 + 1] = f2tf32(p1);
            Ps[(w16 + g + 8) * APAD + c0    ] = f2tf32(p2);
            Ps[(w16 + g + 8) * APAD + c0 + 1] = f2tf32(p3);
        }
        ps0 += __shfl_xor_sync(0xffffffffu, ps0, 1);
        ps0 += __shfl_xor_sync(0xffffffffu, ps0, 2);
        ps1 += __shfl_xor_sync(0xffffffffu, ps1, 1);
        ps1 += __shfl_xor_sync(0xffffffffu, ps1, 2);
        l0 += ps0; l1 += ps1;
        __syncwarp();

        #pragma unroll
        for (int ks = 0; ks < 8; ks++) {
            unsigned a0 = Ps[(w16 + g    ) * APAD + ks * 8 + t];
            unsigned a1 = Ps[(w16 + g + 8) * APAD + ks * 8 + t];
            unsigned a2 = Ps[(w16 + g    ) * APAD + ks * 8 + t + 4];
            unsigned a3 = Ps[(w16 + g + 8) * APAD + ks * 8 + t + 4];
            #pragma unroll
            for (int nt = 0; nt < 8; nt++) {
                unsigned b0 = Vs[(ks * 8 + t    ) * APAD + nt * 8 + g];
                unsigned b1 = Vs[(ks * 8 + t + 4) * APAD + nt * 8 + g];
                mma_tf32(oc[nt], a0, a1, a2, a3, b0, b1);
            }
        }
    }

    float inv0 = 1.0f / l0, inv1 = 1.0f / l1;
    #pragma unroll
    for (int nt = 0; nt < 8; nt++) {
        int col = h * HD + nt * 8 + 2 * t;
        // output consumed ONLY as Wo-GEMM A: pre-round to tf32 grid
        float2 v0 = make_float2(rnd_tf32(oc[nt][0] * inv0), rnd_tf32(oc[nt][1] * inv0));
        float2 v1 = make_float2(rnd_tf32(oc[nt][2] * inv1), rnd_tf32(oc[nt][3] * inv1));
        *(float2*)(O + ((size_t)(b * T_DIM + r0g)) * E_DIM + col) = v0;
        *(float2*)(O + ((size_t)(b * T_DIM + r1g)) * E_DIM + col) = v1;
    }
}

#define ATT_SMEM ((128 * APAD + 64 * APAD + 64 * APAD + 128 * APAD) * 4)

// ---------------- launch ----------------
extern "C" void kernel_launch(void* const* d_in, const int* in_sizes, int n_in,
                              void* d_out, int out_size)
{
    const float* x     = (const float*)d_in[0];
    const float* ln1_g = (const float*)d_in[1];
    const float* ln1_b = (const float*)d_in[2];
    const float* Wq    = (const float*)d_in[3];
    const float* Wk    = (const float*)d_in[4];
    const float* Wv    = (const float*)d_in[5];
    const float* Wo    = (const float*)d_in[6];
    const float* bo    = (const float*)d_in[7];
    const float* ln2_g = (const float*)d_in[8];
    const float* ln2_b = (const float*)d_in[9];
    const float* W1    = (const float*)d_in[10];
    const float* b1    = (const float*)d_in[11];
    const float* W2    = (const float*)d_in[12];
    const float* b2    = (const float*)d_in[13];
    float* out = (float*)d_out;

    float *xn1, *q, *k, *v, *att, *x2, *h2, *ff;
    cudaGetSymbolAddress((void**)&xn1, g_xn1);
    cudaGetSymbolAddress((void**)&q,   g_q);
    cudaGetSymbolAddress((void**)&k,   g_k);
    cudaGetSymbolAddress((void**)&v,   g_v);
    cudaGetSymbolAddress((void**)&att, g_att);
    cudaGetSymbolAddress((void**)&x2,  g_x2);
    cudaGetSymbolAddress((void**)&h2,  g_h2);
    cudaGetSymbolAddress((void**)&ff,  g_ff);

    static int cfg = 0;
    if (!cfg) {
        cudaFuncSetAttribute(attn_tc, cudaFuncAttributeMaxDynamicSharedMemorySize, ATT_SMEM);
        cudaFuncSetAttribute(gemm_qkv, cudaFuncAttributeMaxDynamicSharedMemorySize, GEMM_SMEM);
        cudaFuncSetAttribute(gemm_tf32<2>, cudaFuncAttributeMaxDynamicSharedMemorySize, GEMM_SMEM);
        cudaFuncSetAttribute(gemm_tf32<3>, cudaFuncAttributeMaxDynamicSharedMemorySize, GEMM_SMEM);
        cfg = 1;
    }

    dim3 gE(E_DIM / 128, NROWS / 128);          // (8, 32)
    dim3 gQKV(E_DIM / 128, NROWS / 128, 3);     // (8, 32, 3)
    dim3 gF(FF_DIM / 128, NROWS / 128);         // (32, 32)

    ln_kernel<<<NROWS, 256>>>(x, ln1_g, ln1_b, xn1);
    gemm_qkv<<<gQKV, 256, GEMM_SMEM>>>(xn1, Wq, Wk, Wv, q, k, v, NROWS, E_DIM, E_DIM);
    attn_tc<<<dim3(T_DIM / 128, HEADS, B_DIM), 256, ATT_SMEM>>>(q, k, v, att);
    gemm_tf32<3><<<gE, 256, GEMM_SMEM>>>(att, Wo, bo, x, x2, NROWS, E_DIM, E_DIM);
    ln_kernel<<<NROWS, 256>>>(x2, ln2_g, ln2_b, h2);
    gemm_tf32<2><<<gF, 256, GEMM_SMEM>>>(h2, W1, b1, nullptr, ff, NROWS, FF_DIM, E_DIM);
    gemm_tf32<3><<<gE, 256, GEMM_SMEM>>>(ff, W2, b2, x2, out, NROWS, E_DIM, FF_DIM);
}

// round 8
// speedup vs baseline: 7.1838x; 2.3622x over previous
#include <cuda_runtime.h>
#include <cuda_fp16.h>

#define B_DIM   2
#define T_DIM   2048
#define E_DIM   1024
#define HEADS   16
#define HD      64
#define NROWS   (B_DIM * T_DIM)   // 4096
#define FF_DIM  (4 * E_DIM)       // 4096

// ---------------- scratch (no allocations allowed) ----------------
__device__ __half g_xn1[NROWS * E_DIM];
__device__ __half g_q  [NROWS * E_DIM];
__device__ __half g_k  [NROWS * E_DIM];
__device__ __half g_v  [NROWS * E_DIM];
__device__ __half g_att[NROWS * E_DIM];
__device__ float  g_x2 [NROWS * E_DIM];
__device__ __half g_h2 [NROWS * E_DIM];
__device__ __half g_ff [NROWS * FF_DIM];
// fp16 weights (converted at launch)
__device__ __half g_wq[E_DIM * E_DIM];
__device__ __half g_wk[E_DIM * E_DIM];
__device__ __half g_wv[E_DIM * E_DIM];
__device__ __half g_wo[E_DIM * E_DIM];
__device__ __half g_w1[E_DIM * FF_DIM];
__device__ __half g_w2[FF_DIM * E_DIM];

// ---------------- helpers ----------------
__device__ __forceinline__ void mma_f16(float* c, const unsigned* a,
                                        unsigned b0, unsigned b1)
{
    asm volatile(
        "mma.sync.aligned.m16n8k16.row.col.f32.f16.f16.f32 "
        "{%0,%1,%2,%3}, {%4,%5,%6,%7}, {%8,%9}, {%0,%1,%2,%3};"
        : "+f"(c[0]), "+f"(c[1]), "+f"(c[2]), "+f"(c[3])
        : "r"(a[0]), "r"(a[1]), "r"(a[2]), "r"(a[3]), "r"(b0), "r"(b1));
}
__device__ __forceinline__ void ldm_x4(unsigned* r, unsigned addr) {
    asm volatile("ldmatrix.sync.aligned.m8n8.x4.shared.b16 {%0,%1,%2,%3}, [%4];"
                 : "=r"(r[0]), "=r"(r[1]), "=r"(r[2]), "=r"(r[3]) : "r"(addr));
}
__device__ __forceinline__ void ldm_x4_t(unsigned* r, unsigned addr) {
    asm volatile("ldmatrix.sync.aligned.m8n8.x4.trans.shared.b16 {%0,%1,%2,%3}, [%4];"
                 : "=r"(r[0]), "=r"(r[1]), "=r"(r[2]), "=r"(r[3]) : "r"(addr));
}
__device__ __forceinline__ void cp_async16(unsigned smem_dst, const void* gmem_src) {
    asm volatile("cp.async.cg.shared.global [%0], [%1], 16;" :: "r"(smem_dst), "l"(gmem_src));
}
#define CP_COMMIT()  asm volatile("cp.async.commit_group;" ::: "memory")
#define CP_WAIT1()   asm volatile("cp.async.wait_group 1;" ::: "memory")

// ---------------- fp32 -> fp16 weight conversion ----------------
__global__ void f2h(const float* __restrict__ s, __half* __restrict__ d) {
    int i = (blockIdx.x * blockDim.x + threadIdx.x) * 4;
    float4 v = *(const float4*)(s + i);
    __half2 h0 = __floats2half2_rn(v.x, v.y);
    __half2 h1 = __floats2half2_rn(v.z, v.w);
    uint2 u = make_uint2(*(unsigned*)&h0, *(unsigned*)&h1);
    *(uint2*)(d + i) = u;
}

// ---------------- LayerNorm: one block per row, fp16 output ----------------
__global__ void ln_kernel(const float* __restrict__ X,
                          const float* __restrict__ gw,
                          const float* __restrict__ bw,
                          __half* __restrict__ Y)
{
    int row = blockIdx.x;
    int tid = threadIdx.x;                 // 256 threads, 4 floats each
    const float4* x4 = (const float4*)(X + (size_t)row * E_DIM);
    float4 v = x4[tid];
    float s  = v.x + v.y + v.z + v.w;
    float s2 = v.x*v.x + v.y*v.y + v.z*v.z + v.w*v.w;
    #pragma unroll
    for (int o = 16; o > 0; o >>= 1) {
        s  += __shfl_xor_sync(0xffffffffu, s,  o);
        s2 += __shfl_xor_sync(0xffffffffu, s2, o);
    }
    __shared__ float ss[8], ss2[8];
    int w = tid >> 5;
    if ((tid & 31) == 0) { ss[w] = s; ss2[w] = s2; }
    __syncthreads();
    if (w == 0) {
        s  = ss [tid & 7];
        s2 = ss2[tid & 7];
        #pragma unroll
        for (int o = 4; o > 0; o >>= 1) {
            s  += __shfl_xor_sync(0xffffffffu, s,  o);
            s2 += __shfl_xor_sync(0xffffffffu, s2, o);
        }
        if (tid == 0) { ss[0] = s; ss2[0] = s2; }
    }
    __syncthreads();
    float mu  = ss[0]  * (1.0f / E_DIM);
    float var = ss2[0] * (1.0f / E_DIM) - mu * mu;
    float r   = rsqrtf(var + 1e-5f);
    float4 g4 = ((const float4*)gw)[tid];
    float4 b4 = ((const float4*)bw)[tid];
    __half2 h0 = __floats2half2_rn((v.x - mu) * r * g4.x + b4.x,
                                   (v.y - mu) * r * g4.y + b4.y);
    __half2 h1 = __floats2half2_rn((v.z - mu) * r * g4.z + b4.z,
                                   (v.w - mu) * r * g4.w + b4.w);
    uint2 u = make_uint2(*(unsigned*)&h0, *(unsigned*)&h1);
    *(uint2*)(Y + (size_t)row * E_DIM + 4 * tid) = u;
}

// ---------------- FP16 tensor-core GEMM (cp.async 3-stage, ldmatrix) ------
// C(MxN) = A(MxK) @ B(KxN). A,B fp16; fp32 accum. Block 128x128, BK=32,
// 256 thr = 8 warps (2x4), warp tile 64x32, mma m16n8k16.
// EPI: 0 = none (half out), 2 = bias+relu (half out), 3 = bias+residual (float out)
#define AH_STRIDE 40          // 32 + 8 pad (halves)
#define BH_STRIDE 136         // 128 + 8 pad (halves)
#define STG_A_H (128 * AH_STRIDE)
#define STG_B_H (32 * BH_STRIDE)
#define GEMM_SMEM (3 * (STG_A_H + STG_B_H) * 2)

template<int EPI, typename OutT>
__device__ __forceinline__ void gemm_body(
    const __half* __restrict__ A, const __half* __restrict__ Bm,
    const float* __restrict__ bias, const float* __restrict__ res,
    OutT* __restrict__ C, int M, int N, int K, __half* smh)
{
    unsigned aB = (unsigned)__cvta_generic_to_shared(smh);
    unsigned bB = aB + 3 * STG_A_H * 2;

    int tid  = threadIdx.x;
    int lane = tid & 31;
    int warp = tid >> 5;
    int wm   = warp >> 2;        // 0..1
    int wn   = warp & 3;         // 0..3
    int g    = lane >> 2;        // 0..7
    int t    = lane & 3;         // 0..3
    int bm   = blockIdx.y * 128;
    int bn   = blockIdx.x * 128;

    // staging maps (16B = 8 halves per cp.async)
    int arow0 = tid >> 2,  aoff = (tid & 3) * 8;          // + second chunk at +64 rows
    int brow0 = tid >> 4,  boff = (tid & 15) * 8;         // + second chunk at +16 rows

    const __half* Abase = A + (size_t)(bm + arow0) * K + aoff;
    const __half* Bbase = Bm + (size_t)brow0 * N + bn + boff;
    size_t a64 = (size_t)64 * K;
    size_t b16 = (size_t)16 * N;

    float acc[4][4][4];
    #pragma unroll
    for (int mt = 0; mt < 4; mt++)
        #pragma unroll
        for (int nt = 0; nt < 4; nt++)
            #pragma unroll
            for (int e = 0; e < 4; e++) acc[mt][nt][e] = 0.f;

    int NIT = K >> 5;   // BK = 32

    // precomputed smem fragment addresses (byte offsets within a stage)
    unsigned a_frag_base[4];
    #pragma unroll
    for (int mt = 0; mt < 4; mt++)
        a_frag_base[mt] = aB + ((wm * 64 + mt * 16 + (lane & 15)) * AH_STRIDE
                                + (lane >> 4) * 8) * 2;
    unsigned b_frag_base[2];
    #pragma unroll
    for (int np = 0; np < 2; np++) {
        int krow = (lane & 7) + ((lane >> 3) & 1) * 8;
        int ncol = wn * 32 + np * 16 + ((lane >= 16) ? 8 : 0);
        b_frag_base[np] = bB + (krow * BH_STRIDE + ncol) * 2;
    }

    // prologue: stages 0,1
    #pragma unroll
    for (int s = 0; s < 2; s++) {
        int k0 = s * 32;
        cp_async16(aB + (s * STG_A_H + arow0 * AH_STRIDE + aoff) * 2,        Abase + k0);
        cp_async16(aB + (s * STG_A_H + (arow0 + 64) * AH_STRIDE + aoff) * 2, Abase + k0 + a64);
        cp_async16(bB + (s * STG_B_H + brow0 * BH_STRIDE + boff) * 2,        Bbase + (size_t)k0 * N);
        cp_async16(bB + (s * STG_B_H + (brow0 + 16) * BH_STRIDE + boff) * 2, Bbase + (size_t)(k0 + 16) * N);
        CP_COMMIT();
    }

    for (int it = 0; it < NIT; it++) {
        CP_WAIT1();
        __syncthreads();

        int nf = it + 2;
        if (nf < NIT) {
            int sf = nf % 3;
            int k0 = nf * 32;
            cp_async16(aB + (sf * STG_A_H + arow0 * AH_STRIDE + aoff) * 2,        Abase + k0);
            cp_async16(aB + (sf * STG_A_H + (arow0 + 64) * AH_STRIDE + aoff) * 2, Abase + k0 + a64);
            cp_async16(bB + (sf * STG_B_H + brow0 * BH_STRIDE + boff) * 2,        Bbase + (size_t)k0 * N);
            cp_async16(bB + (sf * STG_B_H + (brow0 + 16) * BH_STRIDE + boff) * 2, Bbase + (size_t)(k0 + 16) * N);
        }
        CP_COMMIT();

        int s = it % 3;
        unsigned aStage = (unsigned)(s * STG_A_H * 2);
        unsigned bStage = (unsigned)(s * STG_B_H * 2);
        #pragma unroll
        for (int ks = 0; ks < 2; ks++) {
            unsigned af[4][4], bf[2][4];
            #pragma unroll
            for (int mt = 0; mt < 4; mt++)
                ldm_x4(af[mt], a_frag_base[mt] + aStage + ks * 16 * 2);
            #pragma unroll
            for (int np = 0; np < 2; np++)
                ldm_x4_t(bf[np], b_frag_base[np] + bStage + ks * 16 * BH_STRIDE * 2);
            #pragma unroll
            for (int mt = 0; mt < 4; mt++)
                #pragma unroll
                for (int nt = 0; nt < 4; nt++)
                    mma_f16(acc[mt][nt], af[mt], bf[nt >> 1][(nt & 1) * 2],
                            bf[nt >> 1][(nt & 1) * 2 + 1]);
        }
    }

    // epilogue
    #pragma unroll
    for (int mt = 0; mt < 4; mt++) {
        int r0 = bm + wm * 64 + mt * 16 + g;
        int r1 = r0 + 8;
        #pragma unroll
        for (int nt = 0; nt < 4; nt++) {
            int col = bn + wn * 32 + nt * 8 + 2 * t;
            float2 v0 = make_float2(acc[mt][nt][0], acc[mt][nt][1]);
            float2 v1 = make_float2(acc[mt][nt][2], acc[mt][nt][3]);
            if (EPI >= 2) {
                float2 bb = *(const float2*)(bias + col);
                v0.x += bb.x; v0.y += bb.y;
                v1.x += bb.x; v1.y += bb.y;
            }
            if (EPI == 2) {
                v0.x = fmaxf(v0.x, 0.f); v0.y = fmaxf(v0.y, 0.f);
                v1.x = fmaxf(v1.x, 0.f); v1.y = fmaxf(v1.y, 0.f);
            }
            if constexpr (EPI == 3) {
                float2 r0v = *(const float2*)(res + (size_t)r0 * N + col);
                float2 r1v = *(const float2*)(res + (size_t)r1 * N + col);
                v0.x += r0v.x; v0.y += r0v.y;
                v1.x += r1v.x; v1.y += r1v.y;
                *(float2*)((float*)C + (size_t)r0 * N + col) = v0;
                *(float2*)((float*)C + (size_t)r1 * N + col) = v1;
            } else {
                __half2 h0 = __floats2half2_rn(v0.x, v0.y);
                __half2 h1 = __floats2half2_rn(v1.x, v1.y);
                *(__half2*)((__half*)C + (size_t)r0 * N + col) = h0;
                *(__half2*)((__half*)C + (size_t)r1 * N + col) = h1;
            }
        }
    }
}

template<int EPI, typename OutT>
__global__ __launch_bounds__(256, 2)
void gemm_f16(const __half* __restrict__ A, const __half* __restrict__ Bm,
              const float* __restrict__ bias, const float* __restrict__ res,
              OutT* __restrict__ C, int M, int N, int K)
{
    extern __shared__ __half smh[];
    gemm_body<EPI, OutT>(A, Bm, bias, res, C, M, N, K, smh);
}

// fused QKV: blockIdx.z selects weight/output
__global__ __launch_bounds__(256, 2)
void gemm_qkv(const __half* __restrict__ A,
              const __half* __restrict__ B0, const __half* __restrict__ B1,
              const __half* __restrict__ B2,
              __half* __restrict__ C0, __half* __restrict__ C1, __half* __restrict__ C2,
              int M, int N, int K)
{
    extern __shared__ __half smh[];
    const __half* Bm = (blockIdx.z == 0) ? B0 : (blockIdx.z == 1) ? B1 : B2;
    __half*       C  = (blockIdx.z == 0) ? C0 : (blockIdx.z == 1) ? C1 : C2;
    gemm_body<0, __half>(A, Bm, nullptr, nullptr, C, M, N, K, smh);
}

// ---------------- fp16 tensor-core causal flash attention -----------------
// 256 threads = 8 warps; block = 128 q rows of one (b,h); warp w owns rows
// [w*16, w*16+16). KV tiles of 64. mma m16n8k16, ldmatrix fragments.
#define QP 72                  // 64 + 8 pad (halves)
#define ATT_SMEM ((128*QP + 64*QP + 64*QP + 128*QP) * 2)
__global__ __launch_bounds__(256)
void attn_tc(const __half* __restrict__ Q, const __half* __restrict__ K,
             const __half* __restrict__ V, __half* __restrict__ O)
{
    extern __shared__ __half sh[];
    __half* Qs = sh;                    // [128][QP]  q rows x d
    __half* Ks = Qs + 128 * QP;         // [64][QP]   [kv][d]
    __half* Vs = Ks + 64 * QP;          // [64][QP]   [kv][d]
    __half* Ps = Vs + 64 * QP;          // [128][QP]  q rows x kv (64 used)
    unsigned qB = (unsigned)__cvta_generic_to_shared(Qs);
    unsigned kB = (unsigned)__cvta_generic_to_shared(Ks);
    unsigned vB = (unsigned)__cvta_generic_to_shared(Vs);
    unsigned pB = (unsigned)__cvta_generic_to_shared(Ps);

    int b = blockIdx.z, h = blockIdx.y;
    int q0 = blockIdx.x * 128;
    int tid  = threadIdx.x;
    int lane = tid & 31;
    int warp = tid >> 5;
    int g    = lane >> 2;
    int t    = lane & 3;
    int w16  = warp * 16;

    // ---- stage Q tile (128 x 64 halves) ----
    #pragma unroll
    for (int i = 0; i < 4; i++) {
        int c = tid + i * 256;            // 1024 chunks of 8 halves
        int row = c >> 3, off = (c & 7) * 8;
        *(uint4*)&Qs[row * QP + off] =
            *(const uint4*)(Q + ((size_t)(b * T_DIM + q0 + row)) * E_DIM + h * HD + off);
    }
    __syncthreads();

    // ---- hoist Q fragments (const across kv loop): 4 d-ksteps ----
    unsigned qa[4][4];
    #pragma unroll
    for (int dk = 0; dk < 4; dk++)
        ldm_x4(qa[dk], qB + ((w16 + (lane & 15)) * QP + dk * 16 + (lane >> 4) * 8) * 2);

    float oc[8][4];
    #pragma unroll
    for (int nt = 0; nt < 8; nt++)
        #pragma unroll
        for (int e = 0; e < 4; e++) oc[nt][e] = 0.f;
    float m0 = -1e30f, m1 = -1e30f, l0 = 0.f, l1 = 0.f;

    int r0g = q0 + w16 + g;
    int r1g = r0g + 8;

    // fragment address pieces
    int bnrow = (lane & 7) + ((lane >> 3) & 1) * 8;      // non-trans B row part
    int bncol = (lane >= 16) ? 8 : 0;                    // non-trans B col part
    int btrow = (lane & 7) + ((lane >> 3) & 1) * 8;      // trans B k-row part
    int btcol = (lane >= 16) ? 8 : 0;                    // trans B n-col part

    int kend = q0 + 128;
    for (int kt = 0; kt < kend; kt += 64) {
        __syncthreads();
        // ---- stage K and V tiles (64 x 64 halves each) ----
        #pragma unroll
        for (int i = 0; i < 2; i++) {
            int c = tid + i * 256;        // 512 chunks
            int row = c >> 3, off = (c & 7) * 8;
            size_t gidx = ((size_t)(b * T_DIM + kt + row)) * E_DIM + h * HD + off;
            *(uint4*)&Ks[row * QP + off] = *(const uint4*)(K + gidx);
            *(uint4*)&Vs[row * QP + off] = *(const uint4*)(V + gidx);
        }
        __syncthreads();

        // ---- S = Q @ K^T : warp's 16 rows x 64 kv ----
        float sc[8][4];
        #pragma unroll
        for (int nt = 0; nt < 8; nt++)
            #pragma unroll
            for (int e = 0; e < 4; e++) sc[nt][e] = 0.f;

        #pragma unroll
        for (int dk = 0; dk < 4; dk++) {
            #pragma unroll
            for (int np = 0; np < 4; np++) {       // np covers kv tiles 2np, 2np+1
                unsigned kb[4];
                ldm_x4(kb, kB + ((np * 16 + bnrow) * QP + dk * 16 + ((lane >> 3) & 1) * 8
                                 - ((lane >> 3) & 1) * 8               // row part already has k-half? no:
                                 + 0) * 2);
                // NOTE: for non-trans B ([n][k] storage) the k-half comes from (lane>>3)&1
                // which is already folded into bnrow? It must NOT be. Recompute properly:
                (void)kb;
                unsigned addr = kB + ((np * 16 + (lane & 7) + ((lane >= 16) ? 8 : 0)) * QP
                                      + dk * 16 + ((lane >> 3) & 1) * 8) * 2;
                ldm_x4(kb, addr);
                mma_f16(sc[np * 2 + 0], qa[dk], kb[0], kb[1]);
                mma_f16(sc[np * 2 + 1], qa[dk], kb[2], kb[3]);
            }
        }

        // ---- scale + causal mask + online softmax ----
        bool need_mask = (kt + 64 > q0);
        float tm0 = -1e30f, tm1 = -1e30f;
        #pragma unroll
        for (int nt = 0; nt < 8; nt++) {
            int c0 = kt + nt * 8 + 2 * t;
            #pragma unroll
            for (int e = 0; e < 4; e++) {
                float s = sc[nt][e] * 0.125f;
                if (need_mask) {
                    int col = c0 + (e & 1);
                    int row = (e < 2) ? r0g : r1g;
                    if (col > row) s = -1e30f;
                }
                sc[nt][e] = s;
            }
            tm0 = fmaxf(tm0, fmaxf(sc[nt][0], sc[nt][1]));
            tm1 = fmaxf(tm1, fmaxf(sc[nt][2], sc[nt][3]));
        }
        tm0 = fmaxf(tm0, __shfl_xor_sync(0xffffffffu, tm0, 1));
        tm0 = fmaxf(tm0, __shfl_xor_sync(0xffffffffu, tm0, 2));
        tm1 = fmaxf(tm1, __shfl_xor_sync(0xffffffffu, tm1, 1));
        tm1 = fmaxf(tm1, __shfl_xor_sync(0xffffffffu, tm1, 2));

        float mn0 = fmaxf(m0, tm0), mn1 = fmaxf(m1, tm1);
        float al0 = __expf(m0 - mn0), al1 = __expf(m1 - mn1);
        m0 = mn0; m1 = mn1;
        l0 *= al0; l1 *= al1;
        #pragma unroll
        for (int nt = 0; nt < 8; nt++) {
            oc[nt][0] *= al0; oc[nt][1] *= al0;
            oc[nt][2] *= al1; oc[nt][3] *= al1;
        }

        float ps0 = 0.f, ps1 = 0.f;
        #pragma unroll
        for (int nt = 0; nt < 8; nt++) {
            float p0 = __expf(sc[nt][0] - mn0);
            float p1 = __expf(sc[nt][1] - mn0);
            float p2 = __expf(sc[nt][2] - mn1);
            float p3 = __expf(sc[nt][3] - mn1);
            ps0 += p0 + p1; ps1 += p2 + p3;
            int c0 = nt * 8 + 2 * t;
            *(__half2*)&Ps[(w16 + g    ) * QP + c0] = __floats2half2_rn(p0, p1);
            *(__half2*)&Ps[(w16 + g + 8) * QP + c0] = __floats2half2_rn(p2, p3);
        }
        ps0 += __shfl_xor_sync(0xffffffffu, ps0, 1);
        ps0 += __shfl_xor_sync(0xffffffffu, ps0, 2);
        ps1 += __shfl_xor_sync(0xffffffffu, ps1, 1);
        ps1 += __shfl_xor_sync(0xffffffffu, ps1, 2);
        l0 += ps0; l1 += ps1;
        __syncwarp();

        // ---- O += P @ V ----
        #pragma unroll
        for (int ks = 0; ks < 4; ks++) {           // kv k-steps of 16
            unsigned pa[4];
            ldm_x4(pa, pB + ((w16 + (lane & 15)) * QP + ks * 16 + (lane >> 4) * 8) * 2);
            #pragma unroll
            for (int np = 0; np < 4; np++) {       // np covers d tiles 2np, 2np+1
                unsigned vb[4];
                unsigned addr = vB + ((ks * 16 + btrow) * QP + np * 16 + btcol) * 2;
                ldm_x4_t(vb, addr);
                mma_f16(oc[np * 2 + 0], pa, vb[0], vb[1]);
                mma_f16(oc[np * 2 + 1], pa, vb[2], vb[3]);
            }
        }
    }

    // ---- finalize ----
    float inv0 = 1.0f / l0, inv1 = 1.0f / l1;
    #pragma unroll
    for (int nt = 0; nt < 8; nt++) {
        int col = h * HD + nt * 8 + 2 * t;
        __half2 h0 = __floats2half2_rn(oc[nt][0] * inv0, oc[nt][1] * inv0);
        __half2 h1 = __floats2half2_rn(oc[nt][2] * inv1, oc[nt][3] * inv1);
        *(__half2*)(O + ((size_t)(b * T_DIM + r0g)) * E_DIM + col) = h0;
        *(__half2*)(O + ((size_t)(b * T_DIM + r1g)) * E_DIM + col) = h1;
    }
}

// ---------------- launch ----------------
extern "C" void kernel_launch(void* const* d_in, const int* in_sizes, int n_in,
                              void* d_out, int out_size)
{
    const float* x     = (const float*)d_in[0];
    const float* ln1_g = (const float*)d_in[1];
    const float* ln1_b = (const float*)d_in[2];
    const float* Wq    = (const float*)d_in[3];
    const float* Wk    = (const float*)d_in[4];
    const float* Wv    = (const float*)d_in[5];
    const float* Wo    = (const float*)d_in[6];
    const float* bo    = (const float*)d_in[7];
    const float* ln2_g = (const float*)d_in[8];
    const float* ln2_b = (const float*)d_in[9];
    const float* W1    = (const float*)d_in[10];
    const float* b1    = (const float*)d_in[11];
    const float* W2    = (const float*)d_in[12];
    const float* b2    = (const float*)d_in[13];
    float* out = (float*)d_out;

    __half *xn1, *q, *k, *v, *att, *h2, *ff;
    __half *wq, *wk, *wv, *wo, *w1, *w2;
    float  *x2;
    cudaGetSymbolAddress((void**)&xn1, g_xn1);
    cudaGetSymbolAddress((void**)&q,   g_q);
    cudaGetSymbolAddress((void**)&k,   g_k);
    cudaGetSymbolAddress((void**)&v,   g_v);
    cudaGetSymbolAddress((void**)&att, g_att);
    cudaGetSymbolAddress((void**)&x2,  g_x2);
    cudaGetSymbolAddress((void**)&h2,  g_h2);
    cudaGetSymbolAddress((void**)&ff,  g_ff);
    cudaGetSymbolAddress((void**)&wq,  g_wq);
    cudaGetSymbolAddress((void**)&wk,  g_wk);
    cudaGetSymbolAddress((void**)&wv,  g_wv);
    cudaGetSymbolAddress((void**)&wo,  g_wo);
    cudaGetSymbolAddress((void**)&w1,  g_w1);
    cudaGetSymbolAddress((void**)&w2,  g_w2);

    static int cfg = 0;
    if (!cfg) {
        cudaFuncSetAttribute(attn_tc, cudaFuncAttributeMaxDynamicSharedMemorySize, ATT_SMEM);
        cudaFuncSetAttribute(gemm_qkv, cudaFuncAttributeMaxDynamicSharedMemorySize, GEMM_SMEM);
        cudaFuncSetAttribute(gemm_f16<2, __half>, cudaFuncAttributeMaxDynamicSharedMemorySize, GEMM_SMEM);
        cudaFuncSetAttribute(gemm_f16<3, float>, cudaFuncAttributeMaxDynamicSharedMemorySize, GEMM_SMEM);
        cfg = 1;
    }

    // weight conversions (every launch; graph-capturable, deterministic)
    f2h<<<E_DIM * E_DIM / 1024, 256>>>(Wq, wq);
    f2h<<<E_DIM * E_DIM / 1024, 256>>>(Wk, wk);
    f2h<<<E_DIM * E_DIM / 1024, 256>>>(Wv, wv);
    f2h<<<E_DIM * E_DIM / 1024, 256>>>(Wo, wo);
    f2h<<<E_DIM * FF_DIM / 1024, 256>>>(W1, w1);
    f2h<<<FF_DIM * E_DIM / 1024, 256>>>(W2, w2);

    dim3 gE(E_DIM / 128, NROWS / 128);          // (8, 32)
    dim3 gQKV(E_DIM / 128, NROWS / 128, 3);     // (8, 32, 3)
    dim3 gF(FF_DIM / 128, NROWS / 128);         // (32, 32)

    ln_kernel<<<NROWS, 256>>>(x, ln1_g, ln1_b, xn1);
    gemm_qkv<<<gQKV, 256, GEMM_SMEM>>>(xn1, wq, wk, wv, q, k, v, NROWS, E_DIM, E_DIM);
    attn_tc<<<dim3(T_DIM / 128, HEADS, B_DIM), 256, ATT_SMEM>>>(q, k, v, att);
    gemm_f16<3, float><<<gE, 256, GEMM_SMEM>>>(att, wo, bo, x, x2, NROWS, E_DIM, E_DIM);
    ln_kernel<<<NROWS, 256>>>(x2, ln2_g, ln2_b, h2);
    gemm_f16<2, __half><<<gF, 256, GEMM_SMEM>>>(h2, w1, b1, nullptr, ff, NROWS, FF_DIM, E_DIM);
    gemm_f16<3, float><<<gE, 256, GEMM_SMEM>>>(ff, w2, b2, x2, out, NROWS, E_DIM, FF_DIM);
}